// round 10
// baseline (speedup 1.0000x reference)
#include <cuda_runtime.h>
#include <cuda_bf16.h>
#include <cstdint>

#define EPS 1e-5f
typedef unsigned long long ull;
struct ull2x { ull x, y; };

// ---------------------------------------------------------------------------
// Buffers
// ---------------------------------------------------------------------------
// stage1 output as bf16 hi/lo planes, [b][ch][pos/2] (uint32 = 2 adjacent pos)
static __device__ uint32_t g_x1h[256 * 16 * 2048];
static __device__ uint32_t g_x1l[256 * 16 * 2048];
// stage2 output planes, [b][pos][ch/2] (uint32 = 2 adjacent channels)
static __device__ uint32_t g_x2h[256 * 1024 * 16];
static __device__ uint32_t g_x2l[256 * 1024 * 16];
// stage3 pooled ht output f32 [b][pos][ch]
static __device__ float g_buf3f[256 * 256 * 64];

// k1 packed weights (batch-pair lanes)
static __device__ ull pw1[16 * 17];
static __device__ ull psh1[16];

// BN epilogue params for stages 2/3
static __device__ float psc2f[32], pshf2[32];
static __device__ float psc3f[64], pshf3[64];

// B fragments, mma.m16n8k16 per-lane layout. K-orders:
//   conv2: e = ci*10 + k (k=9 is zero pad), K=160
//   conv3: e = k*32 + ci, K=160
static __device__ uint2 gB2frag[10 * 4 * 32];
static __device__ uint2 gB3frag[10 * 8 * 32];

__device__ __forceinline__ float ht(float x) { return fminf(1.f, fmaxf(-1.f, x)); }
__device__ __forceinline__ float sgn(float x) { return (x > 0.f) ? 1.f : ((x < 0.f) ? -1.f : 0.f); }

__device__ __forceinline__ ull fma2(ull a, ull b, ull c) {
    ull d; asm("fma.rn.f32x2 %0, %1, %2, %3;" : "=l"(d) : "l"(a), "l"(b), "l"(c)); return d;
}
__device__ __forceinline__ ull pk(float lo, float hi) {
    ull d; asm("mov.b64 %0, {%1, %2};" : "=l"(d) : "f"(lo), "f"(hi)); return d;
}
__device__ __forceinline__ void upk(ull d, float& lo, float& hi) {
    asm("mov.b64 {%0, %1}, %2;" : "=f"(lo), "=f"(hi) : "l"(d));
}
// pack two f32 -> bf16x2 (first arg in low half)
__device__ __forceinline__ uint32_t cvt2bf(float lo, float hi) {
    uint32_t d; asm("cvt.rn.bf16x2.f32 %0, %1, %2;" : "=r"(d) : "f"(hi), "f"(lo)); return d;
}
__device__ __forceinline__ float bf_lo(uint32_t h) { return __uint_as_float(h << 16); }
__device__ __forceinline__ float bf_hi(uint32_t h) { return __uint_as_float(h & 0xffff0000u); }

__device__ __forceinline__ void mma16816(float* d, uint32_t a0, uint32_t a1,
                                         uint32_t a2, uint32_t a3,
                                         uint32_t b0, uint32_t b1) {
    asm volatile(
        "mma.sync.aligned.m16n8k16.row.col.f32.bf16.bf16.f32 "
        "{%0,%1,%2,%3}, {%4,%5,%6,%7}, {%8,%9}, {%0,%1,%2,%3};"
        : "+f"(d[0]), "+f"(d[1]), "+f"(d[2]), "+f"(d[3])
        : "r"(a0), "r"(a1), "r"(a2), "r"(a3), "r"(b0), "r"(b1));
}

// split y into hi/lo bf16x2 planes
__device__ __forceinline__ void split2(float y0, float y1, uint32_t& h, uint32_t& l) {
    h = cvt2bf(y0, y1);
    l = cvt2bf(y0 - bf_lo(h), y1 - bf_hi(h));
}

// ---------------------------------------------------------------------------
// k0a: k1 weight pack + stage2 BN params + B2 fragments (e = ci*10 + k)
// ---------------------------------------------------------------------------
__global__ void k0a(
    const float* __restrict__ w1,
    const float* __restrict__ g1, const float* __restrict__ b1,
    const float* __restrict__ m1, const float* __restrict__ v1,
    const float* __restrict__ w2,
    const float* __restrict__ g2, const float* __restrict__ b2,
    const float* __restrict__ m2, const float* __restrict__ v2)
{
    const int tid = threadIdx.x;
    for (int i = tid; i < 272; i += 256) {
        int ch = i / 17, k = i % 17;
        float s = g1[ch] * rsqrtf(v1[ch] + EPS);
        float v = w1[ch * 17 + k] * s;
        pw1[i] = pk(v, v);
    }
    if (tid < 16) {
        float s = g1[tid] * rsqrtf(v1[tid] + EPS);
        float t = b1[tid] - m1[tid] * s;
        psh1[tid] = pk(t, t);
    }
    if (tid < 32) {
        float s = g2[tid] * rsqrtf(v2[tid] + EPS);
        psc2f[tid] = s;
        pshf2[tid] = b2[tid] - m2[tid] * s;
    }
    for (int i = tid; i < 10 * 4 * 32; i += 256) {
        int kc = i >> 7, nt = (i >> 5) & 3, l = i & 31;
        int co = nt * 8 + (l >> 2);
        int k0 = kc * 16 + 2 * (l & 3);
        float v[4];
#pragma unroll
        for (int j = 0; j < 4; j++) {
            int e = k0 + (j >> 1) * 8 + (j & 1);
            int ci = e / 10, kk = e % 10;
            v[j] = (kk < 9) ? sgn(w2[co * 144 + ci * 9 + kk]) : 0.f;
        }
        uint2 r;
        r.x = cvt2bf(v[0], v[1]);
        r.y = cvt2bf(v[2], v[3]);
        gB2frag[i] = r;
    }
}

// ---------------------------------------------------------------------------
// k0b: stage3 BN params + B3 fragments (e = k*32 + ci)
// ---------------------------------------------------------------------------
__global__ void k0b(
    const float* __restrict__ w3,
    const float* __restrict__ g3, const float* __restrict__ b3,
    const float* __restrict__ m3, const float* __restrict__ v3)
{
    const int tid = threadIdx.x;
    if (tid < 64) {
        float s = g3[tid] * rsqrtf(v3[tid] + EPS);
        psc3f[tid] = s;
        pshf3[tid] = b3[tid] - m3[tid] * s;
    }
    for (int i = tid; i < 10 * 8 * 32; i += 256) {
        int kc = i >> 8, nt = (i >> 5) & 7, l = i & 31;
        int co = nt * 8 + (l >> 2);
        int k0 = kc * 16 + 2 * (l & 3);
        float v[4];
#pragma unroll
        for (int j = 0; j < 4; j++) {
            int e = k0 + (j >> 1) * 8 + (j & 1);
            int k = e >> 5, ci = e & 31;
            v[j] = sgn(w3[co * 160 + ci * 5 + k]);
        }
        uint2 r;
        r.x = cvt2bf(v[0], v[1]);
        r.y = cvt2bf(v[2], v[3]);
        gB3frag[i] = r;
    }
}

// ---------------------------------------------------------------------------
// Kernel 1: conv1 + BN + ht + pool (FFMA2, batch-pair lanes). Outputs bf16
// hi/lo planes [b][ch][pos/2].
// ---------------------------------------------------------------------------
__global__ __launch_bounds__(128) void k1(const float* __restrict__ x)
{
    __shared__ ull xs[1040];
    __shared__ ull ws[272];
    __shared__ ull sh[16];

    const int bp = blockIdx.y;
    const int p0 = blockIdx.x * 256;
    const int tid = threadIdx.x;

    for (int i = tid; i < 272; i += 128) ws[i] = pw1[i];
    if (tid < 16) sh[tid] = psh1[tid];

    const float* xb0 = x + (2 * bp) * 16384;
    const float* xb1 = xb0 + 16384;
    const int base = 4 * p0 - 8;
    for (int i = tid; i < 1039; i += 128) {
        int gi = base + i;
        xs[i] = (gi >= 0 && gi < 16384) ? pk(xb0[gi], xb1[gi]) : 0ull;
    }
    __syncthreads();

    ull xp[23];
#pragma unroll
    for (int j = 0; j < 11; j++) {
        ull2x t = *(const ull2x*)&xs[8 * tid + 2 * j];
        xp[2 * j] = t.x; xp[2 * j + 1] = t.y;
    }
    xp[22] = xs[8 * tid + 22];

    const int pidx = blockIdx.x * 128 + tid;   // pos/2 index
#pragma unroll 1
    for (int ch = 0; ch < 16; ch++) {
        ull h2 = sh[ch];
        ull a[4] = {h2, h2, h2, h2};
#pragma unroll
        for (int k = 0; k < 17; k++) {
            ull w = ws[ch * 17 + k];
#pragma unroll
            for (int j = 0; j < 4; j++) a[j] = fma2(w, xp[2 * j + k], a[j]);
        }
        float lo[4], hi[4];
#pragma unroll
        for (int j = 0; j < 4; j++) upk(a[j], lo[j], hi[j]);
        // batch lane 0
        {
            float y0 = ht(fmaxf(lo[0], lo[1])), y1 = ht(fmaxf(lo[2], lo[3]));
            uint32_t h, l; split2(y0, y1, h, l);
            g_x1h[((2 * bp) * 16 + ch) * 2048 + pidx] = h;
            g_x1l[((2 * bp) * 16 + ch) * 2048 + pidx] = l;
        }
        // batch lane 1
        {
            float y0 = ht(fmaxf(hi[0], hi[1])), y1 = ht(fmaxf(hi[2], hi[3]));
            uint32_t h, l; split2(y0, y1, h, l);
            g_x1h[((2 * bp + 1) * 16 + ch) * 2048 + pidx] = h;
            g_x1l[((2 * bp + 1) * 16 + ch) * 2048 + pidx] = l;
        }
    }
}

// ---------------------------------------------------------------------------
// Kernel 2: conv2 via mma.sync on precomputed bf16 planes. K-order e=ci*10+k.
// Block: 128 conv pos x 32 ch. grid (16, 256), 128 thr.
// ---------------------------------------------------------------------------
union SmemK2 {
    struct { uint32_t hs[16 * 133]; uint32_t ls[16 * 133]; } in;
    float D[128 * 32];
};

__global__ __launch_bounds__(128) void k2()
{
    __shared__ SmemK2 sm;

    const int tile = blockIdx.x;   // 0..15
    const int b = blockIdx.y;
    const int tid = threadIdx.x;
    const int w = tid >> 5, l = tid & 31;
    const int g = l >> 2, t = l & 3;

    // Stage hi/lo planes: uint32 col c covers gi2 = tile*128 - 2 + c
    {
        const uint32_t* inh = g_x1h + b * 16 * 2048;
        const uint32_t* inl = g_x1l + b * 16 * 2048;
        const int ubase = tile * 128 - 2;
        for (int i = tid; i < 16 * 132; i += 128) {
            int row = i / 132, c = i % 132;
            int gu = ubase + c;
            bool ok = (gu >= 0 && gu < 2048);
            sm.in.hs[row * 133 + c] = ok ? inh[row * 2048 + gu] : 0u;
            sm.in.ls[row * 133 + c] = ok ? inl[row * 2048 + gu] : 0u;
        }
    }
    __syncthreads();

    float D[2][4][4];
#pragma unroll
    for (int mt = 0; mt < 2; mt++)
#pragma unroll
        for (int nt = 0; nt < 4; nt++)
#pragma unroll
            for (int j = 0; j < 4; j++) D[mt][nt][j] = 0.f;

    const int r0 = w * 32 + g;

#pragma unroll
    for (int kc = 0; kc < 10; kc++) {
        uint2 Bf[4];
#pragma unroll
        for (int nt = 0; nt < 4; nt++) Bf[nt] = gB2frag[(kc * 4 + nt) * 32 + l];

        const int e0 = kc * 16 + 2 * t;
        const int e8 = e0 + 8;
        const int o0 = (e0 / 10) * 133 + (e0 % 10) / 2;
        const int o8 = (e8 / 10) * 133 + (e8 % 10) / 2;

#pragma unroll
        for (int mt = 0; mt < 2; mt++) {
            const int r = r0 + mt * 16;
            uint32_t a0 = sm.in.hs[o0 + r], a1 = sm.in.hs[o0 + r + 8];
            uint32_t a2 = sm.in.hs[o8 + r], a3 = sm.in.hs[o8 + r + 8];
            uint32_t c0 = sm.in.ls[o0 + r], c1 = sm.in.ls[o0 + r + 8];
            uint32_t c2 = sm.in.ls[o8 + r], c3 = sm.in.ls[o8 + r + 8];
#pragma unroll
            for (int nt = 0; nt < 4; nt++)
                mma16816(D[mt][nt], a0, a1, a2, a3, Bf[nt].x, Bf[nt].y);
#pragma unroll
            for (int nt = 0; nt < 4; nt++)
                mma16816(D[mt][nt], c0, c1, c2, c3, Bf[nt].x, Bf[nt].y);
        }
    }
    __syncthreads();   // planes dead; reuse as D [128][32]

#pragma unroll
    for (int mt = 0; mt < 2; mt++) {
        int r = w * 32 + mt * 16 + g;
#pragma unroll
        for (int nt = 0; nt < 4; nt++) {
            int c = nt * 8 + 2 * t;
            sm.D[r * 32 + c]           = D[mt][nt][0];
            sm.D[r * 32 + c + 1]       = D[mt][nt][1];
            sm.D[(r + 8) * 32 + c]     = D[mt][nt][2];
            sm.D[(r + 8) * 32 + c + 1] = D[mt][nt][3];
        }
    }
    __syncthreads();

    // BN + ht + maxpool2 -> bf16 planes [b][pos][ch/2]
#pragma unroll
    for (int j = 0; j < 8; j++) {
        int idx = j * 128 + tid;          // 0..1023
        int pr = idx >> 4, cp = idx & 15;
        int c0 = 2 * cp, c1 = c0 + 1;
        float s0 = psc2f[c0], sh0 = pshf2[c0];
        float s1 = psc2f[c1], sh1 = pshf2[c1];
        float ya = fmaxf(ht(fmaf(sm.D[(2 * pr) * 32 + c0], s0, sh0)),
                         ht(fmaf(sm.D[(2 * pr + 1) * 32 + c0], s0, sh0)));
        float yb = fmaxf(ht(fmaf(sm.D[(2 * pr) * 32 + c1], s1, sh1)),
                         ht(fmaf(sm.D[(2 * pr + 1) * 32 + c1], s1, sh1)));
        uint32_t h, lo; split2(ya, yb, h, lo);
        int o = (b * 1024 + tile * 64 + pr) * 16 + cp;
        g_x2h[o] = h;
        g_x2l[o] = lo;
    }
}

// ---------------------------------------------------------------------------
// Kernel 3: conv3 via mma.sync on bf16 planes. K-order e = k*32 + ci.
// Block: 128 conv pos x 64 ch. grid (4, 256), 128 thr.
// ---------------------------------------------------------------------------
union SmemK3 {
    struct { uint32_t hs[259 * 18]; uint32_t ls[259 * 18]; } in;
    float D[128 * 64];
};

__global__ __launch_bounds__(128) void k3()
{
    __shared__ SmemK3 sm;

    const int tile = blockIdx.x;   // 0..3
    const int b = blockIdx.y;
    const int tid = threadIdx.x;
    const int w = tid >> 5, l = tid & 31;
    const int g = l >> 2, t = l & 3;

    const int rbase = tile * 256 - 2;
    for (int i = tid; i < 259 * 16; i += 128) {
        int row = i >> 4, cp = i & 15;
        int gi = rbase + row;
        bool ok = (gi >= 0 && gi < 1024);
        sm.in.hs[row * 18 + cp] = ok ? g_x2h[(b * 1024 + gi) * 16 + cp] : 0u;
        sm.in.ls[row * 18 + cp] = ok ? g_x2l[(b * 1024 + gi) * 16 + cp] : 0u;
    }
    __syncthreads();

    float D[2][8][4];
#pragma unroll
    for (int mt = 0; mt < 2; mt++)
#pragma unroll
        for (int nt = 0; nt < 8; nt++)
#pragma unroll
            for (int j = 0; j < 4; j++) D[mt][nt][j] = 0.f;

    const int r0 = w * 32 + g;   // position row base

#pragma unroll
    for (int kc = 0; kc < 10; kc++) {
        uint2 Bf[8];
#pragma unroll
        for (int nt = 0; nt < 8; nt++) Bf[nt] = gB3frag[(kc * 8 + nt) * 32 + l];

        const int e0 = kc * 16 + 2 * t;
        const int k = e0 >> 5;              // conv tap (same for e0 and e0+8)
        const int u0 = (e0 & 31) >> 1;      // channel pair index
        // A rows in slab coords: row = 2p + k

#pragma unroll
        for (int mt = 0; mt < 2; mt++) {
            const int p = r0 + mt * 16;
            const int ra = (2 * p + k) * 18;
            const int rb = ra + 16 * 18;
            uint32_t a0 = sm.in.hs[ra + u0],     a1 = sm.in.hs[rb + u0];
            uint32_t a2 = sm.in.hs[ra + u0 + 4], a3 = sm.in.hs[rb + u0 + 4];
            uint32_t c0 = sm.in.ls[ra + u0],     c1 = sm.in.ls[rb + u0];
            uint32_t c2 = sm.in.ls[ra + u0 + 4], c3 = sm.in.ls[rb + u0 + 4];
#pragma unroll
            for (int nt = 0; nt < 8; nt++)
                mma16816(D[mt][nt], a0, a1, a2, a3, Bf[nt].x, Bf[nt].y);
#pragma unroll
            for (int nt = 0; nt < 8; nt++)
                mma16816(D[mt][nt], c0, c1, c2, c3, Bf[nt].x, Bf[nt].y);
        }
    }
    __syncthreads();   // planes dead; reuse as D [128][64]

#pragma unroll
    for (int mt = 0; mt < 2; mt++) {
        int r = w * 32 + mt * 16 + g;
#pragma unroll
        for (int nt = 0; nt < 8; nt++) {
            int c = nt * 8 + 2 * t;
            sm.D[r * 64 + c]           = D[mt][nt][0];
            sm.D[r * 64 + c + 1]       = D[mt][nt][1];
            sm.D[(r + 8) * 64 + c]     = D[mt][nt][2];
            sm.D[(r + 8) * 64 + c + 1] = D[mt][nt][3];
        }
    }
    __syncthreads();

#pragma unroll
    for (int j = 0; j < 32; j++) {
        int idx = j * 128 + tid;
        int pr = idx >> 6, c = idx & 63;
        float s = psc3f[c], sh = pshf3[c];
        float y0 = ht(fmaf(sm.D[(2 * pr) * 64 + c], s, sh));
        float y1 = ht(fmaf(sm.D[(2 * pr + 1) * 64 + c], s, sh));
        g_buf3f[(b * 256 + tile * 64 + pr) * 64 + c] = fmaxf(y0, y1);
    }
}

// ---------------------------------------------------------------------------
// Kernel 4: mean over 256 pooled pos, concat rms, fc1 + ht, fc2.
// ---------------------------------------------------------------------------
__global__ __launch_bounds__(64) void k4(
    const float* __restrict__ rms,
    const float* __restrict__ fc1w, const float* __restrict__ fc1b,
    const float* __restrict__ fc2w, const float* __restrict__ fc2b,
    float* __restrict__ out)
{
    __shared__ float comb[65];
    __shared__ float h1[32];
    const int b = blockIdx.x;
    const int tid = threadIdx.x;

    {
        float s = 0.f;
        const float* basep = g_buf3f + b * 256 * 64 + tid;
#pragma unroll 8
        for (int P = 0; P < 256; P++) s += basep[P * 64];
        comb[tid] = s * (1.f / 256.f);
    }
    if (tid == 0) comb[64] = rms[b];
    __syncthreads();

    if (tid < 32) {
        float a = fc1b[tid];
        const float* wr = fc1w + tid * 65;
#pragma unroll
        for (int i = 0; i < 65; i++) a = fmaf(comb[i], wr[i], a);
        h1[tid] = ht(a);
    }
    __syncthreads();

    if (tid < 2) {
        float a = fc2b[tid];
        const float* wr = fc2w + tid * 32;
#pragma unroll
        for (int i = 0; i < 32; i++) a = fmaf(h1[i], wr[i], a);
        out[b * 2 + tid] = a;
    }
}

// ---------------------------------------------------------------------------
extern "C" void kernel_launch(void* const* d_in, const int* in_sizes, int n_in,
                              void* d_out, int out_size)
{
    const float* x     = (const float*)d_in[0];
    const float* rms   = (const float*)d_in[1];
    const float* w1    = (const float*)d_in[2];
    const float* g1    = (const float*)d_in[3];
    const float* b1    = (const float*)d_in[4];
    const float* m1    = (const float*)d_in[5];
    const float* v1    = (const float*)d_in[6];
    const float* w2    = (const float*)d_in[7];
    const float* g2    = (const float*)d_in[8];
    const float* b2    = (const float*)d_in[9];
    const float* m2    = (const float*)d_in[10];
    const float* v2    = (const float*)d_in[11];
    const float* w3    = (const float*)d_in[12];
    const float* g3    = (const float*)d_in[13];
    const float* b3    = (const float*)d_in[14];
    const float* m3    = (const float*)d_in[15];
    const float* v3    = (const float*)d_in[16];
    const float* fc1w  = (const float*)d_in[17];
    const float* fc1b  = (const float*)d_in[18];
    const float* fc2w  = (const float*)d_in[19];
    const float* fc2b  = (const float*)d_in[20];
    float* out = (float*)d_out;

    k0a<<<1, 256>>>(w1, g1, b1, m1, v1, w2, g2, b2, m2, v2);
    k0b<<<1, 256>>>(w3, g3, b3, m3, v3);
    k1<<<dim3(16, 128), 128>>>(x);
    k2<<<dim3(16, 256), 128>>>();
    k3<<<dim3(4, 256), 128>>>();
    k4<<<256, 64>>>(rms, fc1w, fc1b, fc2w, fc2b, out);
}

// round 11
// speedup vs baseline: 1.2949x; 1.2949x over previous
#include <cuda_runtime.h>
#include <cuda_bf16.h>
#include <cstdint>

#define EPS 1e-5f
typedef unsigned long long ull;
struct ull2x { ull x, y; };

// ---------------------------------------------------------------------------
// Buffers
// ---------------------------------------------------------------------------
// stage1 output as bf16 hi/lo planes, [b][ch][pos/2] (uint32 = 2 adjacent pos)
static __device__ uint32_t g_x1h[256 * 16 * 2048];
static __device__ uint32_t g_x1l[256 * 16 * 2048];
// stage2 output planes, [b][pos][ch/2] (uint32 = 2 adjacent channels)
static __device__ uint32_t g_x2h[256 * 1024 * 16];
static __device__ uint32_t g_x2l[256 * 1024 * 16];
// stage3 pooled ht output f32 [b][pos][ch]
static __device__ float g_buf3f[256 * 256 * 64];

// k1 packed weights (batch-pair lanes)
static __device__ ull pw1[16 * 17];
static __device__ ull psh1[16];

// BN epilogue params for stages 2/3
static __device__ float psc2f[32], pshf2[32];
static __device__ float psc3f[64], pshf3[64];

// B fragments, mma.m16n8k16 per-lane layout. K-orders:
//   conv2: e = ci*10 + k (k=9 is zero pad), K=160
//   conv3: e = k*32 + ci, K=160
static __device__ uint2 gB2frag[10 * 4 * 32];
static __device__ uint2 gB3frag[10 * 8 * 32];

__device__ __forceinline__ float ht(float x) { return fminf(1.f, fmaxf(-1.f, x)); }
__device__ __forceinline__ float sgn(float x) { return (x > 0.f) ? 1.f : ((x < 0.f) ? -1.f : 0.f); }

__device__ __forceinline__ ull fma2(ull a, ull b, ull c) {
    ull d; asm("fma.rn.f32x2 %0, %1, %2, %3;" : "=l"(d) : "l"(a), "l"(b), "l"(c)); return d;
}
__device__ __forceinline__ ull pk(float lo, float hi) {
    ull d; asm("mov.b64 %0, {%1, %2};" : "=l"(d) : "f"(lo), "f"(hi)); return d;
}
__device__ __forceinline__ void upk(ull d, float& lo, float& hi) {
    asm("mov.b64 {%0, %1}, %2;" : "=f"(lo), "=f"(hi) : "l"(d));
}
// pack two f32 -> bf16x2 (first arg in low half)
__device__ __forceinline__ uint32_t cvt2bf(float lo, float hi) {
    uint32_t d; asm("cvt.rn.bf16x2.f32 %0, %1, %2;" : "=r"(d) : "f"(hi), "f"(lo)); return d;
}
__device__ __forceinline__ float bf_lo(uint32_t h) { return __uint_as_float(h << 16); }
__device__ __forceinline__ float bf_hi(uint32_t h) { return __uint_as_float(h & 0xffff0000u); }

__device__ __forceinline__ void mma16816(float* d, uint32_t a0, uint32_t a1,
                                         uint32_t a2, uint32_t a3,
                                         uint32_t b0, uint32_t b1) {
    asm volatile(
        "mma.sync.aligned.m16n8k16.row.col.f32.bf16.bf16.f32 "
        "{%0,%1,%2,%3}, {%4,%5,%6,%7}, {%8,%9}, {%0,%1,%2,%3};"
        : "+f"(d[0]), "+f"(d[1]), "+f"(d[2]), "+f"(d[3])
        : "r"(a0), "r"(a1), "r"(a2), "r"(a3), "r"(b0), "r"(b1));
}

__device__ __forceinline__ void split2(float y0, float y1, uint32_t& h, uint32_t& l) {
    h = cvt2bf(y0, y1);
    l = cvt2bf(y0 - bf_lo(h), y1 - bf_hi(h));
}

// ---------------------------------------------------------------------------
// k0a: k1 weight pack + stage2 BN params + B2 fragments (e = ci*10 + k)
// ---------------------------------------------------------------------------
__global__ void k0a(
    const float* __restrict__ w1,
    const float* __restrict__ g1, const float* __restrict__ b1,
    const float* __restrict__ m1, const float* __restrict__ v1,
    const float* __restrict__ w2,
    const float* __restrict__ g2, const float* __restrict__ b2,
    const float* __restrict__ m2, const float* __restrict__ v2)
{
    const int tid = threadIdx.x;
    for (int i = tid; i < 272; i += 256) {
        int ch = i / 17, k = i % 17;
        float s = g1[ch] * rsqrtf(v1[ch] + EPS);
        float v = w1[ch * 17 + k] * s;
        pw1[i] = pk(v, v);
    }
    if (tid < 16) {
        float s = g1[tid] * rsqrtf(v1[tid] + EPS);
        float t = b1[tid] - m1[tid] * s;
        psh1[tid] = pk(t, t);
    }
    if (tid < 32) {
        float s = g2[tid] * rsqrtf(v2[tid] + EPS);
        psc2f[tid] = s;
        pshf2[tid] = b2[tid] - m2[tid] * s;
    }
    for (int i = tid; i < 10 * 4 * 32; i += 256) {
        int kc = i >> 7, nt = (i >> 5) & 3, l = i & 31;
        int co = nt * 8 + (l >> 2);
        int k0 = kc * 16 + 2 * (l & 3);
        float v[4];
#pragma unroll
        for (int j = 0; j < 4; j++) {
            int e = k0 + (j >> 1) * 8 + (j & 1);
            int ci = e / 10, kk = e % 10;
            v[j] = (kk < 9) ? sgn(w2[co * 144 + ci * 9 + kk]) : 0.f;
        }
        uint2 r;
        r.x = cvt2bf(v[0], v[1]);
        r.y = cvt2bf(v[2], v[3]);
        gB2frag[i] = r;
    }
}

// ---------------------------------------------------------------------------
// k0b: stage3 BN params + B3 fragments (e = k*32 + ci)
// ---------------------------------------------------------------------------
__global__ void k0b(
    const float* __restrict__ w3,
    const float* __restrict__ g3, const float* __restrict__ b3,
    const float* __restrict__ m3, const float* __restrict__ v3)
{
    const int tid = threadIdx.x;
    if (tid < 64) {
        float s = g3[tid] * rsqrtf(v3[tid] + EPS);
        psc3f[tid] = s;
        pshf3[tid] = b3[tid] - m3[tid] * s;
    }
    for (int i = tid; i < 10 * 8 * 32; i += 256) {
        int kc = i >> 8, nt = (i >> 5) & 7, l = i & 31;
        int co = nt * 8 + (l >> 2);
        int k0 = kc * 16 + 2 * (l & 3);
        float v[4];
#pragma unroll
        for (int j = 0; j < 4; j++) {
            int e = k0 + (j >> 1) * 8 + (j & 1);
            int k = e >> 5, ci = e & 31;
            v[j] = sgn(w3[co * 160 + ci * 5 + k]);
        }
        uint2 r;
        r.x = cvt2bf(v[0], v[1]);
        r.y = cvt2bf(v[2], v[3]);
        gB3frag[i] = r;
    }
}

// ---------------------------------------------------------------------------
// Kernel 1: conv1 + BN + ht + pool (FFMA2, batch-pair lanes). Outputs bf16
// hi/lo planes [b][ch][pos/2].
// ---------------------------------------------------------------------------
__global__ __launch_bounds__(128) void k1(const float* __restrict__ x)
{
    __shared__ ull xs[1040];
    __shared__ ull ws[272];
    __shared__ ull sh[16];

    const int bp = blockIdx.y;
    const int p0 = blockIdx.x * 256;
    const int tid = threadIdx.x;

    for (int i = tid; i < 272; i += 128) ws[i] = pw1[i];
    if (tid < 16) sh[tid] = psh1[tid];

    const float* xb0 = x + (2 * bp) * 16384;
    const float* xb1 = xb0 + 16384;
    const int base = 4 * p0 - 8;
    for (int i = tid; i < 1039; i += 128) {
        int gi = base + i;
        xs[i] = (gi >= 0 && gi < 16384) ? pk(xb0[gi], xb1[gi]) : 0ull;
    }
    __syncthreads();

    ull xp[23];
#pragma unroll
    for (int j = 0; j < 11; j++) {
        ull2x t = *(const ull2x*)&xs[8 * tid + 2 * j];
        xp[2 * j] = t.x; xp[2 * j + 1] = t.y;
    }
    xp[22] = xs[8 * tid + 22];

    const int pidx = blockIdx.x * 128 + tid;   // pos/2 index
#pragma unroll 1
    for (int ch = 0; ch < 16; ch++) {
        ull h2 = sh[ch];
        ull a[4] = {h2, h2, h2, h2};
#pragma unroll
        for (int k = 0; k < 17; k++) {
            ull w = ws[ch * 17 + k];
#pragma unroll
            for (int j = 0; j < 4; j++) a[j] = fma2(w, xp[2 * j + k], a[j]);
        }
        float lo[4], hi[4];
#pragma unroll
        for (int j = 0; j < 4; j++) upk(a[j], lo[j], hi[j]);
        {
            float y0 = ht(fmaxf(lo[0], lo[1])), y1 = ht(fmaxf(lo[2], lo[3]));
            uint32_t h, l; split2(y0, y1, h, l);
            g_x1h[((2 * bp) * 16 + ch) * 2048 + pidx] = h;
            g_x1l[((2 * bp) * 16 + ch) * 2048 + pidx] = l;
        }
        {
            float y0 = ht(fmaxf(hi[0], hi[1])), y1 = ht(fmaxf(hi[2], hi[3]));
            uint32_t h, l; split2(y0, y1, h, l);
            g_x1h[((2 * bp + 1) * 16 + ch) * 2048 + pidx] = h;
            g_x1l[((2 * bp + 1) * 16 + ch) * 2048 + pidx] = l;
        }
    }
}

// ---------------------------------------------------------------------------
// Kernel 2: conv2 via mma.sync on precomputed bf16 planes. B frags staged to
// smem (no hot-loop LDG). K-order e=ci*10+k. grid (16, 256), 128 thr.
// ---------------------------------------------------------------------------
union SmemK2 {
    struct { uint32_t hs[16 * 133]; uint32_t ls[16 * 133]; } in;
    float D[128 * 32];
};

__global__ __launch_bounds__(128) void k2()
{
    __shared__ SmemK2 sm;
    __shared__ uint2 Bsm[10 * 4 * 32];   // 10 KB

    const int tile = blockIdx.x;   // 0..15
    const int b = blockIdx.y;
    const int tid = threadIdx.x;
    const int w = tid >> 5, l = tid & 31;
    const int g = l >> 2, t = l & 3;

    for (int i = tid; i < 1280; i += 128) Bsm[i] = gB2frag[i];

    {
        const uint32_t* inh = g_x1h + b * 16 * 2048;
        const uint32_t* inl = g_x1l + b * 16 * 2048;
        const int ubase = tile * 128 - 2;
        for (int i = tid; i < 16 * 132; i += 128) {
            int row = i / 132, c = i % 132;
            int gu = ubase + c;
            bool ok = (gu >= 0 && gu < 2048);
            sm.in.hs[row * 133 + c] = ok ? inh[row * 2048 + gu] : 0u;
            sm.in.ls[row * 133 + c] = ok ? inl[row * 2048 + gu] : 0u;
        }
    }
    __syncthreads();

    float D[2][4][4];
#pragma unroll
    for (int mt = 0; mt < 2; mt++)
#pragma unroll
        for (int nt = 0; nt < 4; nt++)
#pragma unroll
            for (int j = 0; j < 4; j++) D[mt][nt][j] = 0.f;

    const int r0 = w * 32 + g;

#pragma unroll 2
    for (int kc = 0; kc < 10; kc++) {
        uint2 Bf[4];
#pragma unroll
        for (int nt = 0; nt < 4; nt++) Bf[nt] = Bsm[(kc * 4 + nt) * 32 + l];

        const int e0 = kc * 16 + 2 * t;
        const int e8 = e0 + 8;
        const int o0 = (e0 / 10) * 133 + (e0 % 10) / 2;
        const int o8 = (e8 / 10) * 133 + (e8 % 10) / 2;

#pragma unroll
        for (int mt = 0; mt < 2; mt++) {
            const int r = r0 + mt * 16;
            uint32_t a0 = sm.in.hs[o0 + r], a1 = sm.in.hs[o0 + r + 8];
            uint32_t a2 = sm.in.hs[o8 + r], a3 = sm.in.hs[o8 + r + 8];
            uint32_t c0 = sm.in.ls[o0 + r], c1 = sm.in.ls[o0 + r + 8];
            uint32_t c2 = sm.in.ls[o8 + r], c3 = sm.in.ls[o8 + r + 8];
#pragma unroll
            for (int nt = 0; nt < 4; nt++)
                mma16816(D[mt][nt], a0, a1, a2, a3, Bf[nt].x, Bf[nt].y);
#pragma unroll
            for (int nt = 0; nt < 4; nt++)
                mma16816(D[mt][nt], c0, c1, c2, c3, Bf[nt].x, Bf[nt].y);
        }
    }
    __syncthreads();   // planes dead; reuse as D [128][32]

#pragma unroll
    for (int mt = 0; mt < 2; mt++) {
        int r = w * 32 + mt * 16 + g;
#pragma unroll
        for (int nt = 0; nt < 4; nt++) {
            int c = nt * 8 + 2 * t;
            sm.D[r * 32 + c]           = D[mt][nt][0];
            sm.D[r * 32 + c + 1]       = D[mt][nt][1];
            sm.D[(r + 8) * 32 + c]     = D[mt][nt][2];
            sm.D[(r + 8) * 32 + c + 1] = D[mt][nt][3];
        }
    }
    __syncthreads();

#pragma unroll
    for (int j = 0; j < 8; j++) {
        int idx = j * 128 + tid;
        int pr = idx >> 4, cp = idx & 15;
        int c0 = 2 * cp, c1 = c0 + 1;
        float s0 = psc2f[c0], sh0 = pshf2[c0];
        float s1 = psc2f[c1], sh1 = pshf2[c1];
        float ya = fmaxf(ht(fmaf(sm.D[(2 * pr) * 32 + c0], s0, sh0)),
                         ht(fmaf(sm.D[(2 * pr + 1) * 32 + c0], s0, sh0)));
        float yb = fmaxf(ht(fmaf(sm.D[(2 * pr) * 32 + c1], s1, sh1)),
                         ht(fmaf(sm.D[(2 * pr + 1) * 32 + c1], s1, sh1)));
        uint32_t h, lo; split2(ya, yb, h, lo);
        int o = (b * 1024 + tile * 64 + pr) * 16 + cp;
        g_x2h[o] = h;
        g_x2l[o] = lo;
    }
}

// ---------------------------------------------------------------------------
// Kernel 3: conv3 via mma.sync on bf16 planes, B frags in smem (dynamic).
// K-order e = k*32 + ci. grid (4, 256), 128 thr.
// Dynamic smem layout: [B3: 20480 B][planes hs/ls: 2*18648 B (reused as D)]
// ---------------------------------------------------------------------------
__global__ __launch_bounds__(128) void k3()
{
    extern __shared__ char dyn3[];
    uint2* Bsm = (uint2*)dyn3;                          // 2560 uint2
    uint32_t* hs = (uint32_t*)(dyn3 + 20480);           // 259*18
    uint32_t* ls = hs + 259 * 18;
    float* Dsm = (float*)(dyn3 + 20480);                // aliases planes

    const int tile = blockIdx.x;   // 0..3
    const int b = blockIdx.y;
    const int tid = threadIdx.x;
    const int w = tid >> 5, l = tid & 31;
    const int g = l >> 2, t = l & 3;

    for (int i = tid; i < 2560; i += 128) Bsm[i] = gB3frag[i];

    const int rbase = tile * 256 - 2;
    for (int i = tid; i < 259 * 16; i += 128) {
        int row = i >> 4, cp = i & 15;
        int gi = rbase + row;
        bool ok = (gi >= 0 && gi < 1024);
        hs[row * 18 + cp] = ok ? g_x2h[(b * 1024 + gi) * 16 + cp] : 0u;
        ls[row * 18 + cp] = ok ? g_x2l[(b * 1024 + gi) * 16 + cp] : 0u;
    }
    __syncthreads();

    float D[2][8][4];
#pragma unroll
    for (int mt = 0; mt < 2; mt++)
#pragma unroll
        for (int nt = 0; nt < 8; nt++)
#pragma unroll
            for (int j = 0; j < 4; j++) D[mt][nt][j] = 0.f;

    const int r0 = w * 32 + g;

#pragma unroll 2
    for (int kc = 0; kc < 10; kc++) {
        uint2 Bf[8];
#pragma unroll
        for (int nt = 0; nt < 8; nt++) Bf[nt] = Bsm[(kc * 8 + nt) * 32 + l];

        const int e0 = kc * 16 + 2 * t;
        const int k = e0 >> 5;
        const int u0 = (e0 & 31) >> 1;

#pragma unroll
        for (int mt = 0; mt < 2; mt++) {
            const int p = r0 + mt * 16;
            const int ra = (2 * p + k) * 18;
            const int rb = ra + 16 * 18;
            uint32_t a0 = hs[ra + u0],     a1 = hs[rb + u0];
            uint32_t a2 = hs[ra + u0 + 4], a3 = hs[rb + u0 + 4];
            uint32_t c0 = ls[ra + u0],     c1 = ls[rb + u0];
            uint32_t c2 = ls[ra + u0 + 4], c3 = ls[rb + u0 + 4];
#pragma unroll
            for (int nt = 0; nt < 8; nt++)
                mma16816(D[mt][nt], a0, a1, a2, a3, Bf[nt].x, Bf[nt].y);
#pragma unroll
            for (int nt = 0; nt < 8; nt++)
                mma16816(D[mt][nt], c0, c1, c2, c3, Bf[nt].x, Bf[nt].y);
        }
    }
    __syncthreads();   // planes dead; reuse as D [128][64]

#pragma unroll
    for (int mt = 0; mt < 2; mt++) {
        int r = w * 32 + mt * 16 + g;
#pragma unroll
        for (int nt = 0; nt < 8; nt++) {
            int c = nt * 8 + 2 * t;
            Dsm[r * 64 + c]           = D[mt][nt][0];
            Dsm[r * 64 + c + 1]       = D[mt][nt][1];
            Dsm[(r + 8) * 64 + c]     = D[mt][nt][2];
            Dsm[(r + 8) * 64 + c + 1] = D[mt][nt][3];
        }
    }
    __syncthreads();

#pragma unroll
    for (int j = 0; j < 32; j++) {
        int idx = j * 128 + tid;
        int pr = idx >> 6, c = idx & 63;
        float s = psc3f[c], sh = pshf3[c];
        float y0 = ht(fmaf(Dsm[(2 * pr) * 64 + c], s, sh));
        float y1 = ht(fmaf(Dsm[(2 * pr + 1) * 64 + c], s, sh));
        g_buf3f[(b * 256 + tile * 64 + pr) * 64 + c] = fmaxf(y0, y1);
    }
}

// ---------------------------------------------------------------------------
// Kernel 4: mean over 256 pooled pos, concat rms, fc1 + ht, fc2.
// ---------------------------------------------------------------------------
__global__ __launch_bounds__(64) void k4(
    const float* __restrict__ rms,
    const float* __restrict__ fc1w, const float* __restrict__ fc1b,
    const float* __restrict__ fc2w, const float* __restrict__ fc2b,
    float* __restrict__ out)
{
    __shared__ float comb[65];
    __shared__ float h1[32];
    const int b = blockIdx.x;
    const int tid = threadIdx.x;

    {
        float s = 0.f;
        const float* basep = g_buf3f + b * 256 * 64 + tid;
#pragma unroll 8
        for (int P = 0; P < 256; P++) s += basep[P * 64];
        comb[tid] = s * (1.f / 256.f);
    }
    if (tid == 0) comb[64] = rms[b];
    __syncthreads();

    if (tid < 32) {
        float a = fc1b[tid];
        const float* wr = fc1w + tid * 65;
#pragma unroll
        for (int i = 0; i < 65; i++) a = fmaf(comb[i], wr[i], a);
        h1[tid] = ht(a);
    }
    __syncthreads();

    if (tid < 2) {
        float a = fc2b[tid];
        const float* wr = fc2w + tid * 32;
#pragma unroll
        for (int i = 0; i < 32; i++) a = fmaf(h1[i], wr[i], a);
        out[b * 2 + tid] = a;
    }
}

// ---------------------------------------------------------------------------
extern "C" void kernel_launch(void* const* d_in, const int* in_sizes, int n_in,
                              void* d_out, int out_size)
{
    const float* x     = (const float*)d_in[0];
    const float* rms   = (const float*)d_in[1];
    const float* w1    = (const float*)d_in[2];
    const float* g1    = (const float*)d_in[3];
    const float* b1    = (const float*)d_in[4];
    const float* m1    = (const float*)d_in[5];
    const float* v1    = (const float*)d_in[6];
    const float* w2    = (const float*)d_in[7];
    const float* g2    = (const float*)d_in[8];
    const float* b2    = (const float*)d_in[9];
    const float* m2    = (const float*)d_in[10];
    const float* v2    = (const float*)d_in[11];
    const float* w3    = (const float*)d_in[12];
    const float* g3    = (const float*)d_in[13];
    const float* b3    = (const float*)d_in[14];
    const float* m3    = (const float*)d_in[15];
    const float* v3    = (const float*)d_in[16];
    const float* fc1w  = (const float*)d_in[17];
    const float* fc1b  = (const float*)d_in[18];
    const float* fc2w  = (const float*)d_in[19];
    const float* fc2b  = (const float*)d_in[20];
    float* out = (float*)d_out;

    const int k3_smem = 20480 + 2 * 259 * 18 * 4;   // 57776 B
    cudaFuncSetAttribute(k3, cudaFuncAttributeMaxDynamicSharedMemorySize, k3_smem);

    k0a<<<1, 256>>>(w1, g1, b1, m1, v1, w2, g2, b2, m2, v2);
    k0b<<<1, 256>>>(w3, g3, b3, m3, v3);
    k1<<<dim3(16, 128), 128>>>(x);
    k2<<<dim3(16, 256), 128>>>();
    k3<<<dim3(4, 256), 128, k3_smem>>>();
    k4<<<256, 64>>>(rms, fc1w, fc1b, fc2w, fc2b, out);
}

// round 12
// speedup vs baseline: 1.3126x; 1.0137x over previous
#include <cuda_runtime.h>
#include <cuda_bf16.h>
#include <cstdint>

#define EPS 1e-5f
typedef unsigned long long ull;
struct ull2x { ull x, y; };

// ---------------------------------------------------------------------------
// Buffers
// ---------------------------------------------------------------------------
// stage1 output as bf16 hi/lo planes, [b][ch][pos/2] (uint32 = 2 adjacent pos)
static __device__ uint32_t g_x1h[256 * 16 * 2048];
static __device__ uint32_t g_x1l[256 * 16 * 2048];
// stage2 output planes, [b][pos][ch/2] (uint32 = 2 adjacent channels)
static __device__ uint32_t g_x2h[256 * 1024 * 16];
static __device__ uint32_t g_x2l[256 * 1024 * 16];
// stage3 pooled ht output f32 [b][pos][ch]
static __device__ float g_buf3f[256 * 256 * 64];

// k1 packed weights (batch-pair lanes)
static __device__ ull pw1[16 * 17];
static __device__ ull psh1[16];

// BN epilogue params for stages 2/3
static __device__ float psc2f[32], pshf2[32];
static __device__ float psc3f[64], pshf3[64];

// B fragments, mma.m16n8k16 per-lane layout. K-orders:
//   conv2: e = ci*10 + k (k=9 is zero pad), K=160
//   conv3: e = k*32 + ci, K=160
static __device__ uint2 gB2frag[10 * 4 * 32];
static __device__ uint2 gB3frag[10 * 8 * 32];

__device__ __forceinline__ float ht(float x) { return fminf(1.f, fmaxf(-1.f, x)); }
__device__ __forceinline__ float sgn(float x) { return (x > 0.f) ? 1.f : ((x < 0.f) ? -1.f : 0.f); }

__device__ __forceinline__ ull fma2(ull a, ull b, ull c) {
    ull d; asm("fma.rn.f32x2 %0, %1, %2, %3;" : "=l"(d) : "l"(a), "l"(b), "l"(c)); return d;
}
__device__ __forceinline__ ull pk(float lo, float hi) {
    ull d; asm("mov.b64 %0, {%1, %2};" : "=l"(d) : "f"(lo), "f"(hi)); return d;
}
__device__ __forceinline__ void upk(ull d, float& lo, float& hi) {
    asm("mov.b64 {%0, %1}, %2;" : "=f"(lo), "=f"(hi) : "l"(d));
}
// pack two f32 -> bf16x2 (first arg in low half)
__device__ __forceinline__ uint32_t cvt2bf(float lo, float hi) {
    uint32_t d; asm("cvt.rn.bf16x2.f32 %0, %1, %2;" : "=r"(d) : "f"(hi), "f"(lo)); return d;
}
__device__ __forceinline__ float bf_lo(uint32_t h) { return __uint_as_float(h << 16); }
__device__ __forceinline__ float bf_hi(uint32_t h) { return __uint_as_float(h & 0xffff0000u); }

__device__ __forceinline__ void mma16816(float* d, uint32_t a0, uint32_t a1,
                                         uint32_t a2, uint32_t a3,
                                         uint32_t b0, uint32_t b1) {
    asm volatile(
        "mma.sync.aligned.m16n8k16.row.col.f32.bf16.bf16.f32 "
        "{%0,%1,%2,%3}, {%4,%5,%6,%7}, {%8,%9}, {%0,%1,%2,%3};"
        : "+f"(d[0]), "+f"(d[1]), "+f"(d[2]), "+f"(d[3])
        : "r"(a0), "r"(a1), "r"(a2), "r"(a3), "r"(b0), "r"(b1));
}

__device__ __forceinline__ void split2(float y0, float y1, uint32_t& h, uint32_t& l) {
    h = cvt2bf(y0, y1);
    l = cvt2bf(y0 - bf_lo(h), y1 - bf_hi(h));
}

// ---------------------------------------------------------------------------
// k0a: k1 weight pack + stage2 BN params + B2 fragments (e = ci*10 + k)
// ---------------------------------------------------------------------------
__global__ void k0a(
    const float* __restrict__ w1,
    const float* __restrict__ g1, const float* __restrict__ b1,
    const float* __restrict__ m1, const float* __restrict__ v1,
    const float* __restrict__ w2,
    const float* __restrict__ g2, const float* __restrict__ b2,
    const float* __restrict__ m2, const float* __restrict__ v2)
{
    const int tid = threadIdx.x;
    for (int i = tid; i < 272; i += 256) {
        int ch = i / 17, k = i % 17;
        float s = g1[ch] * rsqrtf(v1[ch] + EPS);
        float v = w1[ch * 17 + k] * s;
        pw1[i] = pk(v, v);
    }
    if (tid < 16) {
        float s = g1[tid] * rsqrtf(v1[tid] + EPS);
        float t = b1[tid] - m1[tid] * s;
        psh1[tid] = pk(t, t);
    }
    if (tid < 32) {
        float s = g2[tid] * rsqrtf(v2[tid] + EPS);
        psc2f[tid] = s;
        pshf2[tid] = b2[tid] - m2[tid] * s;
    }
    for (int i = tid; i < 10 * 4 * 32; i += 256) {
        int kc = i >> 7, nt = (i >> 5) & 3, l = i & 31;
        int co = nt * 8 + (l >> 2);
        int k0 = kc * 16 + 2 * (l & 3);
        float v[4];
#pragma unroll
        for (int j = 0; j < 4; j++) {
            int e = k0 + (j >> 1) * 8 + (j & 1);
            int ci = e / 10, kk = e % 10;
            v[j] = (kk < 9) ? sgn(w2[co * 144 + ci * 9 + kk]) : 0.f;
        }
        uint2 r;
        r.x = cvt2bf(v[0], v[1]);
        r.y = cvt2bf(v[2], v[3]);
        gB2frag[i] = r;
    }
}

// ---------------------------------------------------------------------------
// k0b: stage3 BN params + B3 fragments (e = k*32 + ci)
// ---------------------------------------------------------------------------
__global__ void k0b(
    const float* __restrict__ w3,
    const float* __restrict__ g3, const float* __restrict__ b3,
    const float* __restrict__ m3, const float* __restrict__ v3)
{
    const int tid = threadIdx.x;
    if (tid < 64) {
        float s = g3[tid] * rsqrtf(v3[tid] + EPS);
        psc3f[tid] = s;
        pshf3[tid] = b3[tid] - m3[tid] * s;
    }
    for (int i = tid; i < 10 * 8 * 32; i += 256) {
        int kc = i >> 8, nt = (i >> 5) & 7, l = i & 31;
        int co = nt * 8 + (l >> 2);
        int k0 = kc * 16 + 2 * (l & 3);
        float v[4];
#pragma unroll
        for (int j = 0; j < 4; j++) {
            int e = k0 + (j >> 1) * 8 + (j & 1);
            int k = e >> 5, ci = e & 31;
            v[j] = sgn(w3[co * 160 + ci * 5 + k]);
        }
        uint2 r;
        r.x = cvt2bf(v[0], v[1]);
        r.y = cvt2bf(v[2], v[3]);
        gB3frag[i] = r;
    }
}

// ---------------------------------------------------------------------------
// Kernel 1: conv1 + BN + ht + pool (FFMA2, batch-pair lanes). Outputs bf16
// hi/lo planes [b][ch][pos/2].
// ---------------------------------------------------------------------------
__global__ __launch_bounds__(128) void k1(const float* __restrict__ x)
{
    __shared__ ull xs[1040];
    __shared__ ull ws[272];
    __shared__ ull sh[16];

    const int bp = blockIdx.y;
    const int p0 = blockIdx.x * 256;
    const int tid = threadIdx.x;

    for (int i = tid; i < 272; i += 128) ws[i] = pw1[i];
    if (tid < 16) sh[tid] = psh1[tid];

    const float* xb0 = x + (2 * bp) * 16384;
    const float* xb1 = xb0 + 16384;
    const int base = 4 * p0 - 8;
    for (int i = tid; i < 1039; i += 128) {
        int gi = base + i;
        xs[i] = (gi >= 0 && gi < 16384) ? pk(xb0[gi], xb1[gi]) : 0ull;
    }
    __syncthreads();

    ull xp[23];
#pragma unroll
    for (int j = 0; j < 11; j++) {
        ull2x t = *(const ull2x*)&xs[8 * tid + 2 * j];
        xp[2 * j] = t.x; xp[2 * j + 1] = t.y;
    }
    xp[22] = xs[8 * tid + 22];

    const int pidx = blockIdx.x * 128 + tid;   // pos/2 index
#pragma unroll 1
    for (int ch = 0; ch < 16; ch++) {
        ull h2 = sh[ch];
        ull a[4] = {h2, h2, h2, h2};
#pragma unroll
        for (int k = 0; k < 17; k++) {
            ull w = ws[ch * 17 + k];
#pragma unroll
            for (int j = 0; j < 4; j++) a[j] = fma2(w, xp[2 * j + k], a[j]);
        }
        float lo[4], hi[4];
#pragma unroll
        for (int j = 0; j < 4; j++) upk(a[j], lo[j], hi[j]);
        {
            float y0 = ht(fmaxf(lo[0], lo[1])), y1 = ht(fmaxf(lo[2], lo[3]));
            uint32_t h, l; split2(y0, y1, h, l);
            g_x1h[((2 * bp) * 16 + ch) * 2048 + pidx] = h;
            g_x1l[((2 * bp) * 16 + ch) * 2048 + pidx] = l;
        }
        {
            float y0 = ht(fmaxf(hi[0], hi[1])), y1 = ht(fmaxf(hi[2], hi[3]));
            uint32_t h, l; split2(y0, y1, h, l);
            g_x1h[((2 * bp + 1) * 16 + ch) * 2048 + pidx] = h;
            g_x1l[((2 * bp + 1) * 16 + ch) * 2048 + pidx] = l;
        }
    }
}

// ---------------------------------------------------------------------------
// Kernel 2: conv2 via mma.sync on bf16 planes, B in smem. 256 thr, 8 warps,
// each warp owns one m16 tile (no mt loop). grid (16, 256).
// ---------------------------------------------------------------------------
union SmemK2 {
    struct { uint32_t hs[16 * 133]; uint32_t ls[16 * 133]; } in;
    float D[128 * 32];
};

__global__ __launch_bounds__(256) void k2()
{
    __shared__ SmemK2 sm;
    __shared__ uint2 Bsm[10 * 4 * 32];   // 10 KB

    const int tile = blockIdx.x;   // 0..15
    const int b = blockIdx.y;
    const int tid = threadIdx.x;
    const int w = tid >> 5, l = tid & 31;
    const int g = l >> 2, t = l & 3;

    for (int i = tid; i < 1280; i += 256) Bsm[i] = gB2frag[i];

    {
        const uint32_t* inh = g_x1h + b * 16 * 2048;
        const uint32_t* inl = g_x1l + b * 16 * 2048;
        const int ubase = tile * 128 - 2;
        for (int i = tid; i < 16 * 132; i += 256) {
            int row = i / 132, c = i % 132;
            int gu = ubase + c;
            bool ok = (gu >= 0 && gu < 2048);
            sm.in.hs[row * 133 + c] = ok ? inh[row * 2048 + gu] : 0u;
            sm.in.ls[row * 133 + c] = ok ? inl[row * 2048 + gu] : 0u;
        }
    }
    __syncthreads();

    float D[4][4];
#pragma unroll
    for (int nt = 0; nt < 4; nt++)
#pragma unroll
        for (int j = 0; j < 4; j++) D[nt][j] = 0.f;

    const int r = w * 16 + g;   // warp owns m-tile w (16 rows)

#pragma unroll 2
    for (int kc = 0; kc < 10; kc++) {
        uint2 Bf[4];
#pragma unroll
        for (int nt = 0; nt < 4; nt++) Bf[nt] = Bsm[(kc * 4 + nt) * 32 + l];

        const int e0 = kc * 16 + 2 * t;
        const int e8 = e0 + 8;
        const int o0 = (e0 / 10) * 133 + (e0 % 10) / 2;
        const int o8 = (e8 / 10) * 133 + (e8 % 10) / 2;

        uint32_t a0 = sm.in.hs[o0 + r], a1 = sm.in.hs[o0 + r + 8];
        uint32_t a2 = sm.in.hs[o8 + r], a3 = sm.in.hs[o8 + r + 8];
        uint32_t c0 = sm.in.ls[o0 + r], c1 = sm.in.ls[o0 + r + 8];
        uint32_t c2 = sm.in.ls[o8 + r], c3 = sm.in.ls[o8 + r + 8];
#pragma unroll
        for (int nt = 0; nt < 4; nt++)
            mma16816(D[nt], a0, a1, a2, a3, Bf[nt].x, Bf[nt].y);
#pragma unroll
        for (int nt = 0; nt < 4; nt++)
            mma16816(D[nt], c0, c1, c2, c3, Bf[nt].x, Bf[nt].y);
    }
    __syncthreads();   // planes dead; reuse as D [128][32]

#pragma unroll
    for (int nt = 0; nt < 4; nt++) {
        int c = nt * 8 + 2 * t;
        sm.D[r * 32 + c]           = D[nt][0];
        sm.D[r * 32 + c + 1]       = D[nt][1];
        sm.D[(r + 8) * 32 + c]     = D[nt][2];
        sm.D[(r + 8) * 32 + c + 1] = D[nt][3];
    }
    __syncthreads();

#pragma unroll
    for (int j = 0; j < 4; j++) {
        int idx = j * 256 + tid;          // 0..1023
        int pr = idx >> 4, cp = idx & 15;
        int c0 = 2 * cp, c1 = c0 + 1;
        float s0 = psc2f[c0], sh0 = pshf2[c0];
        float s1 = psc2f[c1], sh1 = pshf2[c1];
        float ya = fmaxf(ht(fmaf(sm.D[(2 * pr) * 32 + c0], s0, sh0)),
                         ht(fmaf(sm.D[(2 * pr + 1) * 32 + c0], s0, sh0)));
        float yb = fmaxf(ht(fmaf(sm.D[(2 * pr) * 32 + c1], s1, sh1)),
                         ht(fmaf(sm.D[(2 * pr + 1) * 32 + c1], s1, sh1)));
        uint32_t h, lo; split2(ya, yb, h, lo);
        int o = (b * 1024 + tile * 64 + pr) * 16 + cp;
        g_x2h[o] = h;
        g_x2l[o] = lo;
    }
}

// ---------------------------------------------------------------------------
// Kernel 3: conv3 via mma.sync on bf16 planes, B in smem (dynamic). 256 thr,
// 8 warps, each warp owns one m16 tile. K-order e = k*32 + ci. grid (4, 256).
// Dynamic smem: [B3: 20480 B][planes hs/ls: 2*18648 B (reused as D)]
// ---------------------------------------------------------------------------
__global__ __launch_bounds__(256) void k3()
{
    extern __shared__ char dyn3[];
    uint2* Bsm = (uint2*)dyn3;                          // 2560 uint2
    uint32_t* hs = (uint32_t*)(dyn3 + 20480);           // 259*18
    uint32_t* ls = hs + 259 * 18;
    float* Dsm = (float*)(dyn3 + 20480);                // aliases planes

    const int tile = blockIdx.x;   // 0..3
    const int b = blockIdx.y;
    const int tid = threadIdx.x;
    const int w = tid >> 5, l = tid & 31;
    const int g = l >> 2, t = l & 3;

    for (int i = tid; i < 2560; i += 256) Bsm[i] = gB3frag[i];

    const int rbase = tile * 256 - 2;
    for (int i = tid; i < 259 * 16; i += 256) {
        int row = i >> 4, cp = i & 15;
        int gi = rbase + row;
        bool ok = (gi >= 0 && gi < 1024);
        hs[row * 18 + cp] = ok ? g_x2h[(b * 1024 + gi) * 16 + cp] : 0u;
        ls[row * 18 + cp] = ok ? g_x2l[(b * 1024 + gi) * 16 + cp] : 0u;
    }
    __syncthreads();

    float D[8][4];
#pragma unroll
    for (int nt = 0; nt < 8; nt++)
#pragma unroll
        for (int j = 0; j < 4; j++) D[nt][j] = 0.f;

    const int p = w * 16 + g;   // warp owns m-tile w

#pragma unroll 2
    for (int kc = 0; kc < 10; kc++) {
        uint2 Bf[8];
#pragma unroll
        for (int nt = 0; nt < 8; nt++) Bf[nt] = Bsm[(kc * 8 + nt) * 32 + l];

        const int e0 = kc * 16 + 2 * t;
        const int k = e0 >> 5;
        const int u0 = (e0 & 31) >> 1;

        const int ra = (2 * p + k) * 18;
        const int rb = ra + 16 * 18;
        uint32_t a0 = hs[ra + u0],     a1 = hs[rb + u0];
        uint32_t a2 = hs[ra + u0 + 4], a3 = hs[rb + u0 + 4];
        uint32_t c0 = ls[ra + u0],     c1 = ls[rb + u0];
        uint32_t c2 = ls[ra + u0 + 4], c3 = ls[rb + u0 + 4];
#pragma unroll
        for (int nt = 0; nt < 8; nt++)
            mma16816(D[nt], a0, a1, a2, a3, Bf[nt].x, Bf[nt].y);
#pragma unroll
        for (int nt = 0; nt < 8; nt++)
            mma16816(D[nt], c0, c1, c2, c3, Bf[nt].x, Bf[nt].y);
    }
    __syncthreads();   // planes dead; reuse as D [128][64]

#pragma unroll
    for (int nt = 0; nt < 8; nt++) {
        int c = nt * 8 + 2 * t;
        Dsm[p * 64 + c]           = D[nt][0];
        Dsm[p * 64 + c + 1]       = D[nt][1];
        Dsm[(p + 8) * 64 + c]     = D[nt][2];
        Dsm[(p + 8) * 64 + c + 1] = D[nt][3];
    }
    __syncthreads();

#pragma unroll
    for (int j = 0; j < 16; j++) {
        int idx = j * 256 + tid;
        int pr = idx >> 6, c = idx & 63;
        float s = psc3f[c], sh = pshf3[c];
        float y0 = ht(fmaf(Dsm[(2 * pr) * 64 + c], s, sh));
        float y1 = ht(fmaf(Dsm[(2 * pr + 1) * 64 + c], s, sh));
        g_buf3f[(b * 256 + tile * 64 + pr) * 64 + c] = fmaxf(y0, y1);
    }
}

// ---------------------------------------------------------------------------
// Kernel 4: mean over 256 pooled pos, concat rms, fc1 + ht, fc2.
// ---------------------------------------------------------------------------
__global__ __launch_bounds__(64) void k4(
    const float* __restrict__ rms,
    const float* __restrict__ fc1w, const float* __restrict__ fc1b,
    const float* __restrict__ fc2w, const float* __restrict__ fc2b,
    float* __restrict__ out)
{
    __shared__ float comb[65];
    __shared__ float h1[32];
    const int b = blockIdx.x;
    const int tid = threadIdx.x;

    {
        float s = 0.f;
        const float* basep = g_buf3f + b * 256 * 64 + tid;
#pragma unroll 8
        for (int P = 0; P < 256; P++) s += basep[P * 64];
        comb[tid] = s * (1.f / 256.f);
    }
    if (tid == 0) comb[64] = rms[b];
    __syncthreads();

    if (tid < 32) {
        float a = fc1b[tid];
        const float* wr = fc1w + tid * 65;
#pragma unroll
        for (int i = 0; i < 65; i++) a = fmaf(comb[i], wr[i], a);
        h1[tid] = ht(a);
    }
    __syncthreads();

    if (tid < 2) {
        float a = fc2b[tid];
        const float* wr = fc2w + tid * 32;
#pragma unroll
        for (int i = 0; i < 32; i++) a = fmaf(h1[i], wr[i], a);
        out[b * 2 + tid] = a;
    }
}

// ---------------------------------------------------------------------------
extern "C" void kernel_launch(void* const* d_in, const int* in_sizes, int n_in,
                              void* d_out, int out_size)
{
    const float* x     = (const float*)d_in[0];
    const float* rms   = (const float*)d_in[1];
    const float* w1    = (const float*)d_in[2];
    const float* g1    = (const float*)d_in[3];
    const float* b1    = (const float*)d_in[4];
    const float* m1    = (const float*)d_in[5];
    const float* v1    = (const float*)d_in[6];
    const float* w2    = (const float*)d_in[7];
    const float* g2    = (const float*)d_in[8];
    const float* b2    = (const float*)d_in[9];
    const float* m2    = (const float*)d_in[10];
    const float* v2    = (const float*)d_in[11];
    const float* w3    = (const float*)d_in[12];
    const float* g3    = (const float*)d_in[13];
    const float* b3    = (const float*)d_in[14];
    const float* m3    = (const float*)d_in[15];
    const float* v3    = (const float*)d_in[16];
    const float* fc1w  = (const float*)d_in[17];
    const float* fc1b  = (const float*)d_in[18];
    const float* fc2w  = (const float*)d_in[19];
    const float* fc2b  = (const float*)d_in[20];
    float* out = (float*)d_out;

    const int k3_smem = 20480 + 2 * 259 * 18 * 4;   // 57776 B
    cudaFuncSetAttribute(k3, cudaFuncAttributeMaxDynamicSharedMemorySize, k3_smem);

    k0a<<<1, 256>>>(w1, g1, b1, m1, v1, w2, g2, b2, m2, v2);
    k0b<<<1, 256>>>(w3, g3, b3, m3, v3);
    k1<<<dim3(16, 128), 128>>>(x);
    k2<<<dim3(16, 256), 256>>>();
    k3<<<dim3(4, 256), 256, k3_smem>>>();
    k4<<<256, 64>>>(rms, fc1w, fc1b, fc2w, fc2b, out);
}

// round 13
// speedup vs baseline: 1.3411x; 1.0217x over previous
#include <cuda_runtime.h>
#include <cuda_bf16.h>
#include <cstdint>

#define EPS 1e-5f
typedef unsigned long long ull;
struct ull2x { ull x, y; };

// ---------------------------------------------------------------------------
// Buffers
// ---------------------------------------------------------------------------
// stage1 output as bf16 hi/lo planes, [b][ch][pos/2] (uint32 = 2 adjacent pos)
static __device__ uint32_t g_x1h[256 * 16 * 2048];
static __device__ uint32_t g_x1l[256 * 16 * 2048];
// stage2 output planes, [b][pos][ch/2] (uint32 = 2 adjacent channels)
static __device__ uint32_t g_x2h[256 * 1024 * 16];
static __device__ uint32_t g_x2l[256 * 1024 * 16];
// stage3 pooled ht output f32 [b][pos][ch]
static __device__ float g_buf3f[256 * 256 * 64];

// k1 packed weights (batch-pair lanes)
static __device__ ull pw1[16 * 17];
static __device__ ull psh1[16];

// BN epilogue params for stages 2/3
static __device__ float psc2f[32], pshf2[32];
static __device__ float psc3f[64], pshf3[64];

// B fragments, mma.m16n8k16 per-lane layout. K-orders:
//   conv2: e = ci*10 + k (k=9 is zero pad), K=160
//   conv3: e = k*32 + ci, K=160
static __device__ uint2 gB2frag[10 * 4 * 32];
static __device__ uint2 gB3frag[10 * 8 * 32];

__device__ __forceinline__ float ht(float x) { return fminf(1.f, fmaxf(-1.f, x)); }
__device__ __forceinline__ float sgn(float x) { return (x > 0.f) ? 1.f : ((x < 0.f) ? -1.f : 0.f); }

__device__ __forceinline__ ull fma2(ull a, ull b, ull c) {
    ull d; asm("fma.rn.f32x2 %0, %1, %2, %3;" : "=l"(d) : "l"(a), "l"(b), "l"(c)); return d;
}
__device__ __forceinline__ ull pk(float lo, float hi) {
    ull d; asm("mov.b64 %0, {%1, %2};" : "=l"(d) : "f"(lo), "f"(hi)); return d;
}
__device__ __forceinline__ void upk(ull d, float& lo, float& hi) {
    asm("mov.b64 {%0, %1}, %2;" : "=f"(lo), "=f"(hi) : "l"(d));
}
// pack two f32 -> bf16x2 (first arg in low half)
__device__ __forceinline__ uint32_t cvt2bf(float lo, float hi) {
    uint32_t d; asm("cvt.rn.bf16x2.f32 %0, %1, %2;" : "=r"(d) : "f"(hi), "f"(lo)); return d;
}
__device__ __forceinline__ float bf_lo(uint32_t h) { return __uint_as_float(h << 16); }
__device__ __forceinline__ float bf_hi(uint32_t h) { return __uint_as_float(h & 0xffff0000u); }

__device__ __forceinline__ void mma16816(float* d, uint32_t a0, uint32_t a1,
                                         uint32_t a2, uint32_t a3,
                                         uint32_t b0, uint32_t b1) {
    asm volatile(
        "mma.sync.aligned.m16n8k16.row.col.f32.bf16.bf16.f32 "
        "{%0,%1,%2,%3}, {%4,%5,%6,%7}, {%8,%9}, {%0,%1,%2,%3};"
        : "+f"(d[0]), "+f"(d[1]), "+f"(d[2]), "+f"(d[3])
        : "r"(a0), "r"(a1), "r"(a2), "r"(a3), "r"(b0), "r"(b1));
}

__device__ __forceinline__ void split2(float y0, float y1, uint32_t& h, uint32_t& l) {
    h = cvt2bf(y0, y1);
    l = cvt2bf(y0 - bf_lo(h), y1 - bf_hi(h));
}

// ---------------------------------------------------------------------------
// k0a: k1 weight pack + stage2 BN params + B2 fragments (e = ci*10 + k)
// ---------------------------------------------------------------------------
__global__ void k0a(
    const float* __restrict__ w1,
    const float* __restrict__ g1, const float* __restrict__ b1,
    const float* __restrict__ m1, const float* __restrict__ v1,
    const float* __restrict__ w2,
    const float* __restrict__ g2, const float* __restrict__ b2,
    const float* __restrict__ m2, const float* __restrict__ v2)
{
    const int tid = threadIdx.x;
    for (int i = tid; i < 272; i += 256) {
        int ch = i / 17, k = i % 17;
        float s = g1[ch] * rsqrtf(v1[ch] + EPS);
        float v = w1[ch * 17 + k] * s;
        pw1[i] = pk(v, v);
    }
    if (tid < 16) {
        float s = g1[tid] * rsqrtf(v1[tid] + EPS);
        float t = b1[tid] - m1[tid] * s;
        psh1[tid] = pk(t, t);
    }
    if (tid < 32) {
        float s = g2[tid] * rsqrtf(v2[tid] + EPS);
        psc2f[tid] = s;
        pshf2[tid] = b2[tid] - m2[tid] * s;
    }
    for (int i = tid; i < 10 * 4 * 32; i += 256) {
        int kc = i >> 7, nt = (i >> 5) & 3, l = i & 31;
        int co = nt * 8 + (l >> 2);
        int k0 = kc * 16 + 2 * (l & 3);
        float v[4];
#pragma unroll
        for (int j = 0; j < 4; j++) {
            int e = k0 + (j >> 1) * 8 + (j & 1);
            int ci = e / 10, kk = e % 10;
            v[j] = (kk < 9) ? sgn(w2[co * 144 + ci * 9 + kk]) : 0.f;
        }
        uint2 r;
        r.x = cvt2bf(v[0], v[1]);
        r.y = cvt2bf(v[2], v[3]);
        gB2frag[i] = r;
    }
}

// ---------------------------------------------------------------------------
// k0b: stage3 BN params + B3 fragments (e = k*32 + ci)
// ---------------------------------------------------------------------------
__global__ void k0b(
    const float* __restrict__ w3,
    const float* __restrict__ g3, const float* __restrict__ b3,
    const float* __restrict__ m3, const float* __restrict__ v3)
{
    const int tid = threadIdx.x;
    if (tid < 64) {
        float s = g3[tid] * rsqrtf(v3[tid] + EPS);
        psc3f[tid] = s;
        pshf3[tid] = b3[tid] - m3[tid] * s;
    }
    for (int i = tid; i < 10 * 8 * 32; i += 256) {
        int kc = i >> 8, nt = (i >> 5) & 7, l = i & 31;
        int co = nt * 8 + (l >> 2);
        int k0 = kc * 16 + 2 * (l & 3);
        float v[4];
#pragma unroll
        for (int j = 0; j < 4; j++) {
            int e = k0 + (j >> 1) * 8 + (j & 1);
            int k = e >> 5, ci = e & 31;
            v[j] = sgn(w3[co * 160 + ci * 5 + k]);
        }
        uint2 r;
        r.x = cvt2bf(v[0], v[1]);
        r.y = cvt2bf(v[2], v[3]);
        gB3frag[i] = r;
    }
}

// ---------------------------------------------------------------------------
// Kernel 1: conv1 + BN + ht + pool (FFMA2, batch-pair lanes). Outputs bf16
// hi/lo planes [b][ch][pos/2].
// ---------------------------------------------------------------------------
__global__ __launch_bounds__(128) void k1(const float* __restrict__ x)
{
    __shared__ ull xs[1040];
    __shared__ ull ws[272];
    __shared__ ull sh[16];

    const int bp = blockIdx.y;
    const int p0 = blockIdx.x * 256;
    const int tid = threadIdx.x;

    for (int i = tid; i < 272; i += 128) ws[i] = pw1[i];
    if (tid < 16) sh[tid] = psh1[tid];

    const float* xb0 = x + (2 * bp) * 16384;
    const float* xb1 = xb0 + 16384;
    const int base = 4 * p0 - 8;
    for (int i = tid; i < 1039; i += 128) {
        int gi = base + i;
        xs[i] = (gi >= 0 && gi < 16384) ? pk(xb0[gi], xb1[gi]) : 0ull;
    }
    __syncthreads();

    ull xp[23];
#pragma unroll
    for (int j = 0; j < 11; j++) {
        ull2x t = *(const ull2x*)&xs[8 * tid + 2 * j];
        xp[2 * j] = t.x; xp[2 * j + 1] = t.y;
    }
    xp[22] = xs[8 * tid + 22];

    const int pidx = blockIdx.x * 128 + tid;   // pos/2 index
#pragma unroll 1
    for (int ch = 0; ch < 16; ch++) {
        ull h2 = sh[ch];
        ull a[4] = {h2, h2, h2, h2};
#pragma unroll
        for (int k = 0; k < 17; k++) {
            ull w = ws[ch * 17 + k];
#pragma unroll
            for (int j = 0; j < 4; j++) a[j] = fma2(w, xp[2 * j + k], a[j]);
        }
        float lo[4], hi[4];
#pragma unroll
        for (int j = 0; j < 4; j++) upk(a[j], lo[j], hi[j]);
        {
            float y0 = ht(fmaxf(lo[0], lo[1])), y1 = ht(fmaxf(lo[2], lo[3]));
            uint32_t h, l; split2(y0, y1, h, l);
            g_x1h[((2 * bp) * 16 + ch) * 2048 + pidx] = h;
            g_x1l[((2 * bp) * 16 + ch) * 2048 + pidx] = l;
        }
        {
            float y0 = ht(fmaxf(hi[0], hi[1])), y1 = ht(fmaxf(hi[2], hi[3]));
            uint32_t h, l; split2(y0, y1, h, l);
            g_x1h[((2 * bp + 1) * 16 + ch) * 2048 + pidx] = h;
            g_x1l[((2 * bp + 1) * 16 + ch) * 2048 + pidx] = l;
        }
    }
}

// ---------------------------------------------------------------------------
// Kernel 2: conv2 via mma.sync on bf16 planes, B in smem. 256 thr, 8 warps,
// warp owns one m16 tile. Register epilogue: BN+ht, maxpool via shfl_xor(4)
// (rows r and r+1 live in lanes l and l^4), direct global store.
// ---------------------------------------------------------------------------
struct SmemK2 { uint32_t hs[16 * 133]; uint32_t ls[16 * 133]; };

__global__ __launch_bounds__(256) void k2()
{
    __shared__ SmemK2 sm;
    __shared__ uint2 Bsm[10 * 4 * 32];   // 10 KB

    const int tile = blockIdx.x;   // 0..15
    const int b = blockIdx.y;
    const int tid = threadIdx.x;
    const int w = tid >> 5, l = tid & 31;
    const int g = l >> 2, t = l & 3;

    for (int i = tid; i < 1280; i += 256) Bsm[i] = gB2frag[i];

    {
        const uint32_t* inh = g_x1h + b * 16 * 2048;
        const uint32_t* inl = g_x1l + b * 16 * 2048;
        const int ubase = tile * 128 - 2;
        for (int i = tid; i < 16 * 132; i += 256) {
            int row = i / 132, c = i % 132;
            int gu = ubase + c;
            bool ok = (gu >= 0 && gu < 2048);
            sm.hs[row * 133 + c] = ok ? inh[row * 2048 + gu] : 0u;
            sm.ls[row * 133 + c] = ok ? inl[row * 2048 + gu] : 0u;
        }
    }
    __syncthreads();

    float D[4][4];
#pragma unroll
    for (int nt = 0; nt < 4; nt++)
#pragma unroll
        for (int j = 0; j < 4; j++) D[nt][j] = 0.f;

    const int r = w * 16 + g;   // warp owns m-tile w (16 rows)

#pragma unroll 2
    for (int kc = 0; kc < 10; kc++) {
        uint2 Bf[4];
#pragma unroll
        for (int nt = 0; nt < 4; nt++) Bf[nt] = Bsm[(kc * 4 + nt) * 32 + l];

        const int e0 = kc * 16 + 2 * t;
        const int e8 = e0 + 8;
        const int o0 = (e0 / 10) * 133 + (e0 % 10) / 2;
        const int o8 = (e8 / 10) * 133 + (e8 % 10) / 2;

        uint32_t a0 = sm.hs[o0 + r], a1 = sm.hs[o0 + r + 8];
        uint32_t a2 = sm.hs[o8 + r], a3 = sm.hs[o8 + r + 8];
        uint32_t c0 = sm.ls[o0 + r], c1 = sm.ls[o0 + r + 8];
        uint32_t c2 = sm.ls[o8 + r], c3 = sm.ls[o8 + r + 8];
#pragma unroll
        for (int nt = 0; nt < 4; nt++)
            mma16816(D[nt], a0, a1, a2, a3, Bf[nt].x, Bf[nt].y);
#pragma unroll
        for (int nt = 0; nt < 4; nt++)
            mma16816(D[nt], c0, c1, c2, c3, Bf[nt].x, Bf[nt].y);
    }

    // Register epilogue: BN + ht, pool rows (r, r^1) via shfl_xor(4).
    const bool writer = ((l & 4) == 0);     // even g
    const int prl = w * 8 + (g >> 1);       // local pooled row for d[0],d[1]
#pragma unroll
    for (int nt = 0; nt < 4; nt++) {
        const int c0 = nt * 8 + 2 * t, c1 = c0 + 1;
        const float s0 = psc2f[c0], b0 = pshf2[c0];
        const float s1 = psc2f[c1], b1 = pshf2[c1];
        float y0 = ht(fmaf(D[nt][0], s0, b0));
        float y1 = ht(fmaf(D[nt][1], s1, b1));
        float y2 = ht(fmaf(D[nt][2], s0, b0));
        float y3 = ht(fmaf(D[nt][3], s1, b1));
        float p0 = fmaxf(y0, __shfl_xor_sync(0xffffffffu, y0, 4));
        float p1 = fmaxf(y1, __shfl_xor_sync(0xffffffffu, y1, 4));
        float p2 = fmaxf(y2, __shfl_xor_sync(0xffffffffu, y2, 4));
        float p3 = fmaxf(y3, __shfl_xor_sync(0xffffffffu, y3, 4));
        if (writer) {
            const int cp = nt * 4 + t;
            uint32_t h, lo;
            int o = (b * 1024 + tile * 64 + prl) * 16 + cp;
            split2(p0, p1, h, lo);
            g_x2h[o] = h; g_x2l[o] = lo;
            split2(p2, p3, h, lo);
            g_x2h[o + 4 * 16] = h; g_x2l[o + 4 * 16] = lo;
        }
    }
}

// ---------------------------------------------------------------------------
// Kernel 3: conv3 via mma.sync on bf16 planes, B in smem (dynamic). 256 thr,
// warp owns one m16 tile. Register epilogue with shfl pooling, float2 stores.
// K-order e = k*32 + ci. grid (4, 256).
// ---------------------------------------------------------------------------
__global__ __launch_bounds__(256) void k3()
{
    extern __shared__ char dyn3[];
    uint2* Bsm = (uint2*)dyn3;                          // 2560 uint2, 20480 B
    uint32_t* hs = (uint32_t*)(dyn3 + 20480);           // 259*18
    uint32_t* ls = hs + 259 * 18;

    const int tile = blockIdx.x;   // 0..3
    const int b = blockIdx.y;
    const int tid = threadIdx.x;
    const int w = tid >> 5, l = tid & 31;
    const int g = l >> 2, t = l & 3;

    for (int i = tid; i < 2560; i += 256) Bsm[i] = gB3frag[i];

    const int rbase = tile * 256 - 2;
    for (int i = tid; i < 259 * 16; i += 256) {
        int row = i >> 4, cp = i & 15;
        int gi = rbase + row;
        bool ok = (gi >= 0 && gi < 1024);
        hs[row * 18 + cp] = ok ? g_x2h[(b * 1024 + gi) * 16 + cp] : 0u;
        ls[row * 18 + cp] = ok ? g_x2l[(b * 1024 + gi) * 16 + cp] : 0u;
    }
    __syncthreads();

    float D[8][4];
#pragma unroll
    for (int nt = 0; nt < 8; nt++)
#pragma unroll
        for (int j = 0; j < 4; j++) D[nt][j] = 0.f;

    const int p = w * 16 + g;   // warp owns m-tile w

#pragma unroll 2
    for (int kc = 0; kc < 10; kc++) {
        uint2 Bf[8];
#pragma unroll
        for (int nt = 0; nt < 8; nt++) Bf[nt] = Bsm[(kc * 8 + nt) * 32 + l];

        const int e0 = kc * 16 + 2 * t;
        const int k = e0 >> 5;
        const int u0 = (e0 & 31) >> 1;

        const int ra = (2 * p + k) * 18;
        const int rb = ra + 16 * 18;
        uint32_t a0 = hs[ra + u0],     a1 = hs[rb + u0];
        uint32_t a2 = hs[ra + u0 + 4], a3 = hs[rb + u0 + 4];
        uint32_t c0 = ls[ra + u0],     c1 = ls[rb + u0];
        uint32_t c2 = ls[ra + u0 + 4], c3 = ls[rb + u0 + 4];
#pragma unroll
        for (int nt = 0; nt < 8; nt++)
            mma16816(D[nt], a0, a1, a2, a3, Bf[nt].x, Bf[nt].y);
#pragma unroll
        for (int nt = 0; nt < 8; nt++)
            mma16816(D[nt], c0, c1, c2, c3, Bf[nt].x, Bf[nt].y);
    }

    // Register epilogue: BN + ht, shfl pooling, float2 direct stores.
    const bool writer = ((l & 4) == 0);
    const int prl = w * 8 + (g >> 1);
#pragma unroll
    for (int nt = 0; nt < 8; nt++) {
        const int c0 = nt * 8 + 2 * t, c1 = c0 + 1;
        const float s0 = psc3f[c0], b0 = pshf3[c0];
        const float s1 = psc3f[c1], b1 = pshf3[c1];
        float y0 = ht(fmaf(D[nt][0], s0, b0));
        float y1 = ht(fmaf(D[nt][1], s1, b1));
        float y2 = ht(fmaf(D[nt][2], s0, b0));
        float y3 = ht(fmaf(D[nt][3], s1, b1));
        float p0 = fmaxf(y0, __shfl_xor_sync(0xffffffffu, y0, 4));
        float p1 = fmaxf(y1, __shfl_xor_sync(0xffffffffu, y1, 4));
        float p2 = fmaxf(y2, __shfl_xor_sync(0xffffffffu, y2, 4));
        float p3 = fmaxf(y3, __shfl_xor_sync(0xffffffffu, y3, 4));
        if (writer) {
            int P0 = b * 256 + tile * 64 + prl;
            *(float2*)&g_buf3f[P0 * 64 + c0] = make_float2(p0, p1);
            *(float2*)&g_buf3f[(P0 + 4) * 64 + c0] = make_float2(p2, p3);
        }
    }
}

// ---------------------------------------------------------------------------
// Kernel 4: mean over 256 pooled pos, concat rms, fc1 + ht, fc2.
// ---------------------------------------------------------------------------
__global__ __launch_bounds__(64) void k4(
    const float* __restrict__ rms,
    const float* __restrict__ fc1w, const float* __restrict__ fc1b,
    const float* __restrict__ fc2w, const float* __restrict__ fc2b,
    float* __restrict__ out)
{
    __shared__ float comb[65];
    __shared__ float h1[32];
    const int b = blockIdx.x;
    const int tid = threadIdx.x;

    {
        float s = 0.f;
        const float* basep = g_buf3f + b * 256 * 64 + tid;
#pragma unroll 8
        for (int P = 0; P < 256; P++) s += basep[P * 64];
        comb[tid] = s * (1.f / 256.f);
    }
    if (tid == 0) comb[64] = rms[b];
    __syncthreads();

    if (tid < 32) {
        float a = fc1b[tid];
        const float* wr = fc1w + tid * 65;
#pragma unroll
        for (int i = 0; i < 65; i++) a = fmaf(comb[i], wr[i], a);
        h1[tid] = ht(a);
    }
    __syncthreads();

    if (tid < 2) {
        float a = fc2b[tid];
        const float* wr = fc2w + tid * 32;
#pragma unroll
        for (int i = 0; i < 32; i++) a = fmaf(h1[i], wr[i], a);
        out[b * 2 + tid] = a;
    }
}

// ---------------------------------------------------------------------------
extern "C" void kernel_launch(void* const* d_in, const int* in_sizes, int n_in,
                              void* d_out, int out_size)
{
    const float* x     = (const float*)d_in[0];
    const float* rms   = (const float*)d_in[1];
    const float* w1    = (const float*)d_in[2];
    const float* g1    = (const float*)d_in[3];
    const float* b1    = (const float*)d_in[4];
    const float* m1    = (const float*)d_in[5];
    const float* v1    = (const float*)d_in[6];
    const float* w2    = (const float*)d_in[7];
    const float* g2    = (const float*)d_in[8];
    const float* b2    = (const float*)d_in[9];
    const float* m2    = (const float*)d_in[10];
    const float* v2    = (const float*)d_in[11];
    const float* w3    = (const float*)d_in[12];
    const float* g3    = (const float*)d_in[13];
    const float* b3    = (const float*)d_in[14];
    const float* m3    = (const float*)d_in[15];
    const float* v3    = (const float*)d_in[16];
    const float* fc1w  = (const float*)d_in[17];
    const float* fc1b  = (const float*)d_in[18];
    const float* fc2w  = (const float*)d_in[19];
    const float* fc2b  = (const float*)d_in[20];
    float* out = (float*)d_out;

    const int k3_smem = 20480 + 2 * 259 * 18 * 4;   // 57776 B
    cudaFuncSetAttribute(k3, cudaFuncAttributeMaxDynamicSharedMemorySize, k3_smem);

    k0a<<<1, 256>>>(w1, g1, b1, m1, v1, w2, g2, b2, m2, v2);
    k0b<<<1, 256>>>(w3, g3, b3, m3, v3);
    k1<<<dim3(16, 128), 128>>>(x);
    k2<<<dim3(16, 256), 256>>>();
    k3<<<dim3(4, 256), 256, k3_smem>>>();
    k4<<<256, 64>>>(rms, fc1w, fc1b, fc2w, fc2b, out);
}

// round 14
// speedup vs baseline: 1.3730x; 1.0238x over previous
#include <cuda_runtime.h>
#include <cuda_bf16.h>
#include <cstdint>

#define EPS 1e-5f
typedef unsigned long long ull;
struct ull2x { ull x, y; };

// ---------------------------------------------------------------------------
// Buffers
// ---------------------------------------------------------------------------
// stage1 output: interleaved bf16 hi/lo planes. [b][ch][pos/2] -> uint2(h,l)
static __device__ uint2 g_x1hl[256 * 16 * 2048];
// stage2 output: [b][pos][ch/2] -> uint2(h,l)
static __device__ uint2 g_x2hl[256 * 1024 * 16];
// stage3 pooled ht output f32 [b][pos][ch]
static __device__ float g_buf3f[256 * 256 * 64];

// k1 packed weights (batch-pair lanes)
static __device__ ull pw1[16 * 17];
static __device__ ull psh1[16];

// BN epilogue params for stages 2/3
static __device__ float psc2f[32], pshf2[32];
static __device__ float psc3f[64], pshf3[64];

// B fragments, mma.m16n8k16 per-lane layout. K-orders:
//   conv2: e = ci*10 + k (k=9 is zero pad), K=160
//   conv3: e = k*32 + ci, K=160
static __device__ uint2 gB2frag[10 * 4 * 32];
static __device__ uint2 gB3frag[10 * 8 * 32];

__device__ __forceinline__ float ht(float x) { return fminf(1.f, fmaxf(-1.f, x)); }
__device__ __forceinline__ float sgn(float x) { return (x > 0.f) ? 1.f : ((x < 0.f) ? -1.f : 0.f); }

__device__ __forceinline__ ull fma2(ull a, ull b, ull c) {
    ull d; asm("fma.rn.f32x2 %0, %1, %2, %3;" : "=l"(d) : "l"(a), "l"(b), "l"(c)); return d;
}
__device__ __forceinline__ ull pk(float lo, float hi) {
    ull d; asm("mov.b64 %0, {%1, %2};" : "=l"(d) : "f"(lo), "f"(hi)); return d;
}
__device__ __forceinline__ void upk(ull d, float& lo, float& hi) {
    asm("mov.b64 {%0, %1}, %2;" : "=f"(lo), "=f"(hi) : "l"(d));
}
// pack two f32 -> bf16x2 (first arg in low half)
__device__ __forceinline__ uint32_t cvt2bf(float lo, float hi) {
    uint32_t d; asm("cvt.rn.bf16x2.f32 %0, %1, %2;" : "=r"(d) : "f"(hi), "f"(lo)); return d;
}
__device__ __forceinline__ float bf_lo(uint32_t h) { return __uint_as_float(h << 16); }
__device__ __forceinline__ float bf_hi(uint32_t h) { return __uint_as_float(h & 0xffff0000u); }

__device__ __forceinline__ void mma16816(float* d, uint32_t a0, uint32_t a1,
                                         uint32_t a2, uint32_t a3,
                                         uint32_t b0, uint32_t b1) {
    asm volatile(
        "mma.sync.aligned.m16n8k16.row.col.f32.bf16.bf16.f32 "
        "{%0,%1,%2,%3}, {%4,%5,%6,%7}, {%8,%9}, {%0,%1,%2,%3};"
        : "+f"(d[0]), "+f"(d[1]), "+f"(d[2]), "+f"(d[3])
        : "r"(a0), "r"(a1), "r"(a2), "r"(a3), "r"(b0), "r"(b1));
}

__device__ __forceinline__ uint2 split2u(float y0, float y1) {
    uint2 r;
    r.x = cvt2bf(y0, y1);
    r.y = cvt2bf(y0 - bf_lo(r.x), y1 - bf_hi(r.x));
    return r;
}

// ---------------------------------------------------------------------------
// k0a: k1 weight pack + stage2 BN params + B2 fragments (e = ci*10 + k)
// ---------------------------------------------------------------------------
__global__ void k0a(
    const float* __restrict__ w1,
    const float* __restrict__ g1, const float* __restrict__ b1,
    const float* __restrict__ m1, const float* __restrict__ v1,
    const float* __restrict__ w2,
    const float* __restrict__ g2, const float* __restrict__ b2,
    const float* __restrict__ m2, const float* __restrict__ v2)
{
    const int tid = threadIdx.x;
    for (int i = tid; i < 272; i += 256) {
        int ch = i / 17, k = i % 17;
        float s = g1[ch] * rsqrtf(v1[ch] + EPS);
        float v = w1[ch * 17 + k] * s;
        pw1[i] = pk(v, v);
    }
    if (tid < 16) {
        float s = g1[tid] * rsqrtf(v1[tid] + EPS);
        float t = b1[tid] - m1[tid] * s;
        psh1[tid] = pk(t, t);
    }
    if (tid < 32) {
        float s = g2[tid] * rsqrtf(v2[tid] + EPS);
        psc2f[tid] = s;
        pshf2[tid] = b2[tid] - m2[tid] * s;
    }
    for (int i = tid; i < 10 * 4 * 32; i += 256) {
        int kc = i >> 7, nt = (i >> 5) & 3, l = i & 31;
        int co = nt * 8 + (l >> 2);
        int k0 = kc * 16 + 2 * (l & 3);
        float v[4];
#pragma unroll
        for (int j = 0; j < 4; j++) {
            int e = k0 + (j >> 1) * 8 + (j & 1);
            int ci = e / 10, kk = e % 10;
            v[j] = (kk < 9) ? sgn(w2[co * 144 + ci * 9 + kk]) : 0.f;
        }
        uint2 r;
        r.x = cvt2bf(v[0], v[1]);
        r.y = cvt2bf(v[2], v[3]);
        gB2frag[i] = r;
    }
}

// ---------------------------------------------------------------------------
// k0b: stage3 BN params + B3 fragments (e = k*32 + ci)
// ---------------------------------------------------------------------------
__global__ void k0b(
    const float* __restrict__ w3,
    const float* __restrict__ g3, const float* __restrict__ b3,
    const float* __restrict__ m3, const float* __restrict__ v3)
{
    const int tid = threadIdx.x;
    if (tid < 64) {
        float s = g3[tid] * rsqrtf(v3[tid] + EPS);
        psc3f[tid] = s;
        pshf3[tid] = b3[tid] - m3[tid] * s;
    }
    for (int i = tid; i < 10 * 8 * 32; i += 256) {
        int kc = i >> 8, nt = (i >> 5) & 7, l = i & 31;
        int co = nt * 8 + (l >> 2);
        int k0 = kc * 16 + 2 * (l & 3);
        float v[4];
#pragma unroll
        for (int j = 0; j < 4; j++) {
            int e = k0 + (j >> 1) * 8 + (j & 1);
            int k = e >> 5, ci = e & 31;
            v[j] = sgn(w3[co * 160 + ci * 5 + k]);
        }
        uint2 r;
        r.x = cvt2bf(v[0], v[1]);
        r.y = cvt2bf(v[2], v[3]);
        gB3frag[i] = r;
    }
}

// ---------------------------------------------------------------------------
// Kernel 1: conv1 + BN + ht + pool (FFMA2, batch-pair lanes). Outputs
// interleaved hi/lo uint2 planes [b][ch][pos/2].
// ---------------------------------------------------------------------------
__global__ __launch_bounds__(128) void k1(const float* __restrict__ x)
{
    __shared__ ull xs[1040];
    __shared__ ull ws[272];
    __shared__ ull sh[16];

    const int bp = blockIdx.y;
    const int p0 = blockIdx.x * 256;
    const int tid = threadIdx.x;

    for (int i = tid; i < 272; i += 128) ws[i] = pw1[i];
    if (tid < 16) sh[tid] = psh1[tid];

    const float* xb0 = x + (2 * bp) * 16384;
    const float* xb1 = xb0 + 16384;
    const int base = 4 * p0 - 8;
    for (int i = tid; i < 1039; i += 128) {
        int gi = base + i;
        xs[i] = (gi >= 0 && gi < 16384) ? pk(xb0[gi], xb1[gi]) : 0ull;
    }
    __syncthreads();

    ull xp[23];
#pragma unroll
    for (int j = 0; j < 11; j++) {
        ull2x t = *(const ull2x*)&xs[8 * tid + 2 * j];
        xp[2 * j] = t.x; xp[2 * j + 1] = t.y;
    }
    xp[22] = xs[8 * tid + 22];

    const int pidx = blockIdx.x * 128 + tid;   // pos/2 index
#pragma unroll 1
    for (int ch = 0; ch < 16; ch++) {
        ull h2 = sh[ch];
        ull a[4] = {h2, h2, h2, h2};
#pragma unroll
        for (int k = 0; k < 17; k++) {
            ull w = ws[ch * 17 + k];
#pragma unroll
            for (int j = 0; j < 4; j++) a[j] = fma2(w, xp[2 * j + k], a[j]);
        }
        float lo[4], hi[4];
#pragma unroll
        for (int j = 0; j < 4; j++) upk(a[j], lo[j], hi[j]);
        g_x1hl[((2 * bp) * 16 + ch) * 2048 + pidx] =
            split2u(ht(fmaxf(lo[0], lo[1])), ht(fmaxf(lo[2], lo[3])));
        g_x1hl[((2 * bp + 1) * 16 + ch) * 2048 + pidx] =
            split2u(ht(fmaxf(hi[0], hi[1])), ht(fmaxf(hi[2], hi[3])));
    }
}

// ---------------------------------------------------------------------------
// Kernel 2: conv2 via mma.sync, interleaved hi/lo uint2 smem, row-permuted
// M mapping (row g <- pos base+2g, row g+8 <- pos base+2g+1) so the maxpool
// pair lives in one thread (d0/d2, d1/d3). Register epilogue, no shfl.
// 256 thr, 8 warps, warp owns one m16 tile. grid (16, 256).
// ---------------------------------------------------------------------------
__global__ __launch_bounds__(256) void k2()
{
    __shared__ uint2 hl[16 * 133];       // 17 KB interleaved planes
    __shared__ uint2 Bsm[10 * 4 * 32];   // 10 KB

    const int tile = blockIdx.x;   // 0..15
    const int b = blockIdx.y;
    const int tid = threadIdx.x;
    const int w = tid >> 5, l = tid & 31;
    const int g = l >> 2, t = l & 3;

    for (int i = tid; i < 1280; i += 256) Bsm[i] = gB2frag[i];

    {
        const uint2* in = g_x1hl + b * 16 * 2048;
        const int ubase = tile * 128 - 2;
        for (int i = tid; i < 16 * 132; i += 256) {
            int row = i / 132, c = i % 132;
            int gu = ubase + c;
            hl[row * 133 + c] = (gu >= 0 && gu < 2048) ? in[row * 2048 + gu]
                                                       : make_uint2(0u, 0u);
        }
    }
    __syncthreads();

    float D[4][4];
#pragma unroll
    for (int nt = 0; nt < 4; nt++)
#pragma unroll
        for (int j = 0; j < 4; j++) D[nt][j] = 0.f;

    const int pbase = w * 16 + 2 * g;   // pos for row g; row g+8 is pbase+1

#pragma unroll 2
    for (int kc = 0; kc < 10; kc++) {
        uint2 Bf[4];
#pragma unroll
        for (int nt = 0; nt < 4; nt++) Bf[nt] = Bsm[(kc * 4 + nt) * 32 + l];

        const int e0 = kc * 16 + 2 * t;
        const int e8 = e0 + 8;
        const int o0 = (e0 / 10) * 133 + (e0 % 10) / 2;
        const int o8 = (e8 / 10) * 133 + (e8 % 10) / 2;

        uint2 A0 = hl[o0 + pbase], A1 = hl[o0 + pbase + 1];
        uint2 A2 = hl[o8 + pbase], A3 = hl[o8 + pbase + 1];
#pragma unroll
        for (int nt = 0; nt < 4; nt++)
            mma16816(D[nt], A0.x, A1.x, A2.x, A3.x, Bf[nt].x, Bf[nt].y);
#pragma unroll
        for (int nt = 0; nt < 4; nt++)
            mma16816(D[nt], A0.y, A1.y, A2.y, A3.y, Bf[nt].x, Bf[nt].y);
    }

    // Register epilogue: BN + ht on d0..d3, pool (d0,d2) and (d1,d3), store.
    const int prow = b * 1024 + tile * 64 + w * 8 + g;   // pooled position
#pragma unroll
    for (int nt = 0; nt < 4; nt++) {
        const int c0 = nt * 8 + 2 * t, c1 = c0 + 1;
        const float s0 = psc2f[c0], b0 = pshf2[c0];
        const float s1 = psc2f[c1], b1 = pshf2[c1];
        float pa = fmaxf(ht(fmaf(D[nt][0], s0, b0)), ht(fmaf(D[nt][2], s0, b0)));
        float pb = fmaxf(ht(fmaf(D[nt][1], s1, b1)), ht(fmaf(D[nt][3], s1, b1)));
        g_x2hl[prow * 16 + nt * 4 + t] = split2u(pa, pb);
    }
}

// ---------------------------------------------------------------------------
// Kernel 3: conv3 via mma.sync, interleaved uint2 smem (stride 19 pads banks),
// row-permuted M mapping, register epilogue with float2 stores.
// K-order e = k*32 + ci. 256 thr, grid (4, 256). Dynamic smem.
// ---------------------------------------------------------------------------
__global__ __launch_bounds__(256) void k3()
{
    extern __shared__ char dyn3[];
    uint2* Bsm = (uint2*)dyn3;                     // 2560 uint2 = 20480 B
    uint2* hl = (uint2*)(dyn3 + 20480);            // 259*19 uint2

    const int tile = blockIdx.x;   // 0..3
    const int b = blockIdx.y;
    const int tid = threadIdx.x;
    const int w = tid >> 5, l = tid & 31;
    const int g = l >> 2, t = l & 3;

    for (int i = tid; i < 2560; i += 256) Bsm[i] = gB3frag[i];

    const int rbase = tile * 256 - 2;
    for (int i = tid; i < 259 * 16; i += 256) {
        int row = i >> 4, cp = i & 15;
        int gi = rbase + row;
        hl[row * 19 + cp] = (gi >= 0 && gi < 1024)
                          ? g_x2hl[(b * 1024 + gi) * 16 + cp]
                          : make_uint2(0u, 0u);
    }
    __syncthreads();

    float D[8][4];
#pragma unroll
    for (int nt = 0; nt < 8; nt++)
#pragma unroll
        for (int j = 0; j < 4; j++) D[nt][j] = 0.f;

    const int pbase = w * 16 + 2 * g;   // conv pos for row g; row g+8 = pbase+1

#pragma unroll 2
    for (int kc = 0; kc < 10; kc++) {
        uint2 Bf[8];
#pragma unroll
        for (int nt = 0; nt < 8; nt++) Bf[nt] = Bsm[(kc * 8 + nt) * 32 + l];

        const int e0 = kc * 16 + 2 * t;
        const int k = e0 >> 5;
        const int u0 = (e0 & 31) >> 1;

        const int ra = (2 * pbase + k) * 19 + u0;   // row g
        const int rb = ra + 2 * 19;                 // row g+8 (pos+1)
        uint2 A0 = hl[ra],     A1 = hl[rb];
        uint2 A2 = hl[ra + 4], A3 = hl[rb + 4];
#pragma unroll
        for (int nt = 0; nt < 8; nt++)
            mma16816(D[nt], A0.x, A1.x, A2.x, A3.x, Bf[nt].x, Bf[nt].y);
#pragma unroll
        for (int nt = 0; nt < 8; nt++)
            mma16816(D[nt], A0.y, A1.y, A2.y, A3.y, Bf[nt].x, Bf[nt].y);
    }

    // Register epilogue: BN + ht, in-thread pooling, float2 stores.
    const int P = b * 256 + tile * 64 + w * 8 + g;   // pooled position
#pragma unroll
    for (int nt = 0; nt < 8; nt++) {
        const int c0 = nt * 8 + 2 * t, c1 = c0 + 1;
        const float s0 = psc3f[c0], b0 = pshf3[c0];
        const float s1 = psc3f[c1], b1 = pshf3[c1];
        float pa = fmaxf(ht(fmaf(D[nt][0], s0, b0)), ht(fmaf(D[nt][2], s0, b0)));
        float pb = fmaxf(ht(fmaf(D[nt][1], s1, b1)), ht(fmaf(D[nt][3], s1, b1)));
        *(float2*)&g_buf3f[P * 64 + c0] = make_float2(pa, pb);
    }
}

// ---------------------------------------------------------------------------
// Kernel 4: mean over 256 pooled pos, concat rms, fc1 + ht, fc2.
// ---------------------------------------------------------------------------
__global__ __launch_bounds__(64) void k4(
    const float* __restrict__ rms,
    const float* __restrict__ fc1w, const float* __restrict__ fc1b,
    const float* __restrict__ fc2w, const float* __restrict__ fc2b,
    float* __restrict__ out)
{
    __shared__ float comb[65];
    __shared__ float h1[32];
    const int b = blockIdx.x;
    const int tid = threadIdx.x;

    {
        float s = 0.f;
        const float* basep = g_buf3f + b * 256 * 64 + tid;
#pragma unroll 8
        for (int P = 0; P < 256; P++) s += basep[P * 64];
        comb[tid] = s * (1.f / 256.f);
    }
    if (tid == 0) comb[64] = rms[b];
    __syncthreads();

    if (tid < 32) {
        float a = fc1b[tid];
        const float* wr = fc1w + tid * 65;
#pragma unroll
        for (int i = 0; i < 65; i++) a = fmaf(comb[i], wr[i], a);
        h1[tid] = ht(a);
    }
    __syncthreads();

    if (tid < 2) {
        float a = fc2b[tid];
        const float* wr = fc2w + tid * 32;
#pragma unroll
        for (int i = 0; i < 32; i++) a = fmaf(h1[i], wr[i], a);
        out[b * 2 + tid] = a;
    }
}

// ---------------------------------------------------------------------------
extern "C" void kernel_launch(void* const* d_in, const int* in_sizes, int n_in,
                              void* d_out, int out_size)
{
    const float* x     = (const float*)d_in[0];
    const float* rms   = (const float*)d_in[1];
    const float* w1    = (const float*)d_in[2];
    const float* g1    = (const float*)d_in[3];
    const float* b1    = (const float*)d_in[4];
    const float* m1    = (const float*)d_in[5];
    const float* v1    = (const float*)d_in[6];
    const float* w2    = (const float*)d_in[7];
    const float* g2    = (const float*)d_in[8];
    const float* b2    = (const float*)d_in[9];
    const float* m2    = (const float*)d_in[10];
    const float* v2    = (const float*)d_in[11];
    const float* w3    = (const float*)d_in[12];
    const float* g3    = (const float*)d_in[13];
    const float* b3    = (const float*)d_in[14];
    const float* m3    = (const float*)d_in[15];
    const float* v3    = (const float*)d_in[16];
    const float* fc1w  = (const float*)d_in[17];
    const float* fc1b  = (const float*)d_in[18];
    const float* fc2w  = (const float*)d_in[19];
    const float* fc2b  = (const float*)d_in[20];
    float* out = (float*)d_out;

    const int k3_smem = 20480 + 259 * 19 * 8;   // 59848 B
    cudaFuncSetAttribute(k3, cudaFuncAttributeMaxDynamicSharedMemorySize, k3_smem);

    k0a<<<1, 256>>>(w1, g1, b1, m1, v1, w2, g2, b2, m2, v2);
    k0b<<<1, 256>>>(w3, g3, b3, m3, v3);
    k1<<<dim3(16, 128), 128>>>(x);
    k2<<<dim3(16, 256), 256>>>();
    k3<<<dim3(4, 256), 256, k3_smem>>>();
    k4<<<256, 64>>>(rms, fc1w, fc1b, fc2w, fc2b, out);
}

// round 15
// speedup vs baseline: 1.4274x; 1.0396x over previous
#include <cuda_runtime.h>
#include <cuda_bf16.h>
#include <cstdint>

#define EPS 1e-5f
typedef unsigned long long ull;
struct ull2x { ull x, y; };

// ---------------------------------------------------------------------------
// Buffers
// ---------------------------------------------------------------------------
// stage1 output: interleaved bf16 hi/lo planes. [b][ch][pos/2] -> uint2(h,l)
static __device__ uint2 g_x1hl[256 * 16 * 2048];
// stage2 output: [b][pos][ch/2] -> uint2(h,l)
static __device__ uint2 g_x2hl[256 * 1024 * 16];
// stage3 pooled ht output f32 [b][pos][ch]
static __device__ float g_buf3f[256 * 256 * 64];

// k1 packed weights (batch-pair lanes)
static __device__ ull pw1[16 * 17];
static __device__ ull psh1[16];

// BN epilogue params for stages 2/3
static __device__ float psc2f[32], pshf2[32];
static __device__ float psc3f[64], pshf3[64];

// B fragments, mma.m16n8k16 per-lane layout. K-orders:
//   conv2: e = ci*10 + k (k=9 is zero pad), K=160
//   conv3: e = k*32 + ci, K=160
static __device__ uint2 gB2frag[10 * 4 * 32];
static __device__ uint2 gB3frag[10 * 8 * 32];

__device__ __forceinline__ float ht(float x) { return fminf(1.f, fmaxf(-1.f, x)); }
__device__ __forceinline__ float sgn(float x) { return (x > 0.f) ? 1.f : ((x < 0.f) ? -1.f : 0.f); }

__device__ __forceinline__ ull fma2(ull a, ull b, ull c) {
    ull d; asm("fma.rn.f32x2 %0, %1, %2, %3;" : "=l"(d) : "l"(a), "l"(b), "l"(c)); return d;
}
__device__ __forceinline__ ull pk(float lo, float hi) {
    ull d; asm("mov.b64 %0, {%1, %2};" : "=l"(d) : "f"(lo), "f"(hi)); return d;
}
__device__ __forceinline__ void upk(ull d, float& lo, float& hi) {
    asm("mov.b64 {%0, %1}, %2;" : "=f"(lo), "=f"(hi) : "l"(d));
}
// pack two f32 -> bf16x2 (first arg in low half)
__device__ __forceinline__ uint32_t cvt2bf(float lo, float hi) {
    uint32_t d; asm("cvt.rn.bf16x2.f32 %0, %1, %2;" : "=r"(d) : "f"(hi), "f"(lo)); return d;
}
__device__ __forceinline__ float bf_lo(uint32_t h) { return __uint_as_float(h << 16); }
__device__ __forceinline__ float bf_hi(uint32_t h) { return __uint_as_float(h & 0xffff0000u); }

__device__ __forceinline__ void mma16816(float* d, uint32_t a0, uint32_t a1,
                                         uint32_t a2, uint32_t a3,
                                         uint32_t b0, uint32_t b1) {
    asm volatile(
        "mma.sync.aligned.m16n8k16.row.col.f32.bf16.bf16.f32 "
        "{%0,%1,%2,%3}, {%4,%5,%6,%7}, {%8,%9}, {%0,%1,%2,%3};"
        : "+f"(d[0]), "+f"(d[1]), "+f"(d[2]), "+f"(d[3])
        : "r"(a0), "r"(a1), "r"(a2), "r"(a3), "r"(b0), "r"(b1));
}

__device__ __forceinline__ uint2 split2u(float y0, float y1) {
    uint2 r;
    r.x = cvt2bf(y0, y1);
    r.y = cvt2bf(y0 - bf_lo(r.x), y1 - bf_hi(r.x));
    return r;
}

// ---------------------------------------------------------------------------
// k0a: k1 weight pack + stage2 BN params + B2 fragments (e = ci*10 + k)
// ---------------------------------------------------------------------------
__global__ void k0a(
    const float* __restrict__ w1,
    const float* __restrict__ g1, const float* __restrict__ b1,
    const float* __restrict__ m1, const float* __restrict__ v1,
    const float* __restrict__ w2,
    const float* __restrict__ g2, const float* __restrict__ b2,
    const float* __restrict__ m2, const float* __restrict__ v2)
{
    const int tid = threadIdx.x;
    for (int i = tid; i < 272; i += 256) {
        int ch = i / 17, k = i % 17;
        float s = g1[ch] * rsqrtf(v1[ch] + EPS);
        float v = w1[ch * 17 + k] * s;
        pw1[i] = pk(v, v);
    }
    if (tid < 16) {
        float s = g1[tid] * rsqrtf(v1[tid] + EPS);
        float t = b1[tid] - m1[tid] * s;
        psh1[tid] = pk(t, t);
    }
    if (tid < 32) {
        float s = g2[tid] * rsqrtf(v2[tid] + EPS);
        psc2f[tid] = s;
        pshf2[tid] = b2[tid] - m2[tid] * s;
    }
    for (int i = tid; i < 10 * 4 * 32; i += 256) {
        int kc = i >> 7, nt = (i >> 5) & 3, l = i & 31;
        int co = nt * 8 + (l >> 2);
        int k0 = kc * 16 + 2 * (l & 3);
        float v[4];
#pragma unroll
        for (int j = 0; j < 4; j++) {
            int e = k0 + (j >> 1) * 8 + (j & 1);
            int ci = e / 10, kk = e % 10;
            v[j] = (kk < 9) ? sgn(w2[co * 144 + ci * 9 + kk]) : 0.f;
        }
        uint2 r;
        r.x = cvt2bf(v[0], v[1]);
        r.y = cvt2bf(v[2], v[3]);
        gB2frag[i] = r;
    }
}

// ---------------------------------------------------------------------------
// k0b: stage3 BN params + B3 fragments (e = k*32 + ci)
// ---------------------------------------------------------------------------
__global__ void k0b(
    const float* __restrict__ w3,
    const float* __restrict__ g3, const float* __restrict__ b3,
    const float* __restrict__ m3, const float* __restrict__ v3)
{
    const int tid = threadIdx.x;
    if (tid < 64) {
        float s = g3[tid] * rsqrtf(v3[tid] + EPS);
        psc3f[tid] = s;
        pshf3[tid] = b3[tid] - m3[tid] * s;
    }
    for (int i = tid; i < 10 * 8 * 32; i += 256) {
        int kc = i >> 8, nt = (i >> 5) & 7, l = i & 31;
        int co = nt * 8 + (l >> 2);
        int k0 = kc * 16 + 2 * (l & 3);
        float v[4];
#pragma unroll
        for (int j = 0; j < 4; j++) {
            int e = k0 + (j >> 1) * 8 + (j & 1);
            int k = e >> 5, ci = e & 31;
            v[j] = sgn(w3[co * 160 + ci * 5 + k]);
        }
        uint2 r;
        r.x = cvt2bf(v[0], v[1]);
        r.y = cvt2bf(v[2], v[3]);
        gB3frag[i] = r;
    }
}

// ---------------------------------------------------------------------------
// Kernel 1: conv1 + BN + ht + pool (FFMA2, batch-pair lanes). Outputs
// interleaved hi/lo uint2 planes [b][ch][pos/2].
// ---------------------------------------------------------------------------
__global__ __launch_bounds__(128) void k1(const float* __restrict__ x)
{
    __shared__ ull xs[1040];
    __shared__ ull ws[272];
    __shared__ ull sh[16];

    const int bp = blockIdx.y;
    const int p0 = blockIdx.x * 256;
    const int tid = threadIdx.x;

    for (int i = tid; i < 272; i += 128) ws[i] = pw1[i];
    if (tid < 16) sh[tid] = psh1[tid];

    const float* xb0 = x + (2 * bp) * 16384;
    const float* xb1 = xb0 + 16384;
    const int base = 4 * p0 - 8;
    for (int i = tid; i < 1039; i += 128) {
        int gi = base + i;
        xs[i] = (gi >= 0 && gi < 16384) ? pk(xb0[gi], xb1[gi]) : 0ull;
    }
    __syncthreads();

    ull xp[23];
#pragma unroll
    for (int j = 0; j < 11; j++) {
        ull2x t = *(const ull2x*)&xs[8 * tid + 2 * j];
        xp[2 * j] = t.x; xp[2 * j + 1] = t.y;
    }
    xp[22] = xs[8 * tid + 22];

    const int pidx = blockIdx.x * 128 + tid;   // pos/2 index
#pragma unroll 1
    for (int ch = 0; ch < 16; ch++) {
        ull h2 = sh[ch];
        ull a[4] = {h2, h2, h2, h2};
#pragma unroll
        for (int k = 0; k < 17; k++) {
            ull w = ws[ch * 17 + k];
#pragma unroll
            for (int j = 0; j < 4; j++) a[j] = fma2(w, xp[2 * j + k], a[j]);
        }
        float lo[4], hi[4];
#pragma unroll
        for (int j = 0; j < 4; j++) upk(a[j], lo[j], hi[j]);
        g_x1hl[((2 * bp) * 16 + ch) * 2048 + pidx] =
            split2u(ht(fmaxf(lo[0], lo[1])), ht(fmaxf(lo[2], lo[3])));
        g_x1hl[((2 * bp + 1) * 16 + ch) * 2048 + pidx] =
            split2u(ht(fmaxf(hi[0], hi[1])), ht(fmaxf(hi[2], hi[3])));
    }
}

// ---------------------------------------------------------------------------
// Kernel 2: conv2 via mma.sync. M=256 per block, 2 m-tiles per warp; uint2
// interleaved hi/lo smem; row-permuted M mapping -> in-thread maxpool.
// 256 thr, grid (8, 256).
// ---------------------------------------------------------------------------
__global__ __launch_bounds__(256) void k2()
{
    __shared__ uint2 hl[16 * 261];       // 33.4 KB interleaved planes
    __shared__ uint2 Bsm[10 * 4 * 32];   // 10 KB

    const int tile = blockIdx.x;   // 0..7 (256 conv pos each)
    const int b = blockIdx.y;
    const int tid = threadIdx.x;
    const int w = tid >> 5, l = tid & 31;
    const int g = l >> 2, t = l & 3;

    for (int i = tid; i < 1280; i += 256) Bsm[i] = gB2frag[i];

    {
        const uint2* in = g_x1hl + b * 16 * 2048;
        const int ubase = tile * 256 - 2;
        for (int i = tid; i < 16 * 260; i += 256) {
            int row = i / 260, c = i % 260;
            int gu = ubase + c;
            hl[row * 261 + c] = (gu >= 0 && gu < 2048) ? in[row * 2048 + gu]
                                                       : make_uint2(0u, 0u);
        }
    }
    __syncthreads();

    float D[2][4][4];
#pragma unroll
    for (int mt = 0; mt < 2; mt++)
#pragma unroll
        for (int nt = 0; nt < 4; nt++)
#pragma unroll
            for (int j = 0; j < 4; j++) D[mt][nt][j] = 0.f;

#pragma unroll 2
    for (int kc = 0; kc < 10; kc++) {
        uint2 Bf[4];
#pragma unroll
        for (int nt = 0; nt < 4; nt++) Bf[nt] = Bsm[(kc * 4 + nt) * 32 + l];

        const int e0 = kc * 16 + 2 * t;
        const int e8 = e0 + 8;
        const int o0 = (e0 / 10) * 261 + (e0 % 10) / 2;
        const int o8 = (e8 / 10) * 261 + (e8 % 10) / 2;

#pragma unroll
        for (int mt = 0; mt < 2; mt++) {
            const int pb = w * 32 + mt * 16 + 2 * g;  // pos for row g; row g+8 = pb+1
            uint2 A0 = hl[o0 + pb], A1 = hl[o0 + pb + 1];
            uint2 A2 = hl[o8 + pb], A3 = hl[o8 + pb + 1];
#pragma unroll
            for (int nt = 0; nt < 4; nt++)
                mma16816(D[mt][nt], A0.x, A1.x, A2.x, A3.x, Bf[nt].x, Bf[nt].y);
#pragma unroll
            for (int nt = 0; nt < 4; nt++)
                mma16816(D[mt][nt], A0.y, A1.y, A2.y, A3.y, Bf[nt].x, Bf[nt].y);
        }
    }

    // Register epilogue: BN + ht, pool (d0,d2)/(d1,d3) in-thread, store.
#pragma unroll
    for (int mt = 0; mt < 2; mt++) {
        const int prow = b * 1024 + tile * 128 + w * 16 + mt * 8 + g;
#pragma unroll
        for (int nt = 0; nt < 4; nt++) {
            const int c0 = nt * 8 + 2 * t, c1 = c0 + 1;
            const float s0 = psc2f[c0], b0 = pshf2[c0];
            const float s1 = psc2f[c1], b1 = pshf2[c1];
            float pa = fmaxf(ht(fmaf(D[mt][nt][0], s0, b0)), ht(fmaf(D[mt][nt][2], s0, b0)));
            float pb2 = fmaxf(ht(fmaf(D[mt][nt][1], s1, b1)), ht(fmaf(D[mt][nt][3], s1, b1)));
            g_x2hl[prow * 16 + nt * 4 + t] = split2u(pa, pb2);
        }
    }
}

// ---------------------------------------------------------------------------
// Kernel 3: conv3 via mma.sync, interleaved uint2 smem (stride 19), row-
// permuted M mapping, register epilogue with float2 stores.
// K-order e = k*32 + ci. 256 thr, grid (4, 256). Dynamic smem.
// ---------------------------------------------------------------------------
__global__ __launch_bounds__(256) void k3()
{
    extern __shared__ char dyn3[];
    uint2* Bsm = (uint2*)dyn3;                     // 2560 uint2 = 20480 B
    uint2* hl = (uint2*)(dyn3 + 20480);            // 259*19 uint2

    const int tile = blockIdx.x;   // 0..3
    const int b = blockIdx.y;
    const int tid = threadIdx.x;
    const int w = tid >> 5, l = tid & 31;
    const int g = l >> 2, t = l & 3;

    for (int i = tid; i < 2560; i += 256) Bsm[i] = gB3frag[i];

    const int rbase = tile * 256 - 2;
    for (int i = tid; i < 259 * 16; i += 256) {
        int row = i >> 4, cp = i & 15;
        int gi = rbase + row;
        hl[row * 19 + cp] = (gi >= 0 && gi < 1024)
                          ? g_x2hl[(b * 1024 + gi) * 16 + cp]
                          : make_uint2(0u, 0u);
    }
    __syncthreads();

    float D[8][4];
#pragma unroll
    for (int nt = 0; nt < 8; nt++)
#pragma unroll
        for (int j = 0; j < 4; j++) D[nt][j] = 0.f;

    const int pbase = w * 16 + 2 * g;   // conv pos for row g; row g+8 = pbase+1

#pragma unroll 2
    for (int kc = 0; kc < 10; kc++) {
        uint2 Bf[8];
#pragma unroll
        for (int nt = 0; nt < 8; nt++) Bf[nt] = Bsm[(kc * 8 + nt) * 32 + l];

        const int e0 = kc * 16 + 2 * t;
        const int k = e0 >> 5;
        const int u0 = (e0 & 31) >> 1;

        const int ra = (2 * pbase + k) * 19 + u0;   // row g
        const int rb = ra + 2 * 19;                 // row g+8 (pos+1)
        uint2 A0 = hl[ra],     A1 = hl[rb];
        uint2 A2 = hl[ra + 4], A3 = hl[rb + 4];
#pragma unroll
        for (int nt = 0; nt < 8; nt++)
            mma16816(D[nt], A0.x, A1.x, A2.x, A3.x, Bf[nt].x, Bf[nt].y);
#pragma unroll
        for (int nt = 0; nt < 8; nt++)
            mma16816(D[nt], A0.y, A1.y, A2.y, A3.y, Bf[nt].x, Bf[nt].y);
    }

    // Register epilogue: BN + ht, in-thread pooling, float2 stores.
    const int P = b * 256 + tile * 64 + w * 8 + g;   // pooled position
#pragma unroll
    for (int nt = 0; nt < 8; nt++) {
        const int c0 = nt * 8 + 2 * t, c1 = c0 + 1;
        const float s0 = psc3f[c0], b0 = pshf3[c0];
        const float s1 = psc3f[c1], b1 = pshf3[c1];
        float pa = fmaxf(ht(fmaf(D[nt][0], s0, b0)), ht(fmaf(D[nt][2], s0, b0)));
        float pb = fmaxf(ht(fmaf(D[nt][1], s1, b1)), ht(fmaf(D[nt][3], s1, b1)));
        *(float2*)&g_buf3f[P * 64 + c0] = make_float2(pa, pb);
    }
}

// ---------------------------------------------------------------------------
// Kernel 4: mean over 256 pooled pos, concat rms, fc1 + ht, fc2. 256 threads:
// 4-way split of the position sum, smem reduce.
// ---------------------------------------------------------------------------
__global__ __launch_bounds__(256) void k4(
    const float* __restrict__ rms,
    const float* __restrict__ fc1w, const float* __restrict__ fc1b,
    const float* __restrict__ fc2w, const float* __restrict__ fc2b,
    float* __restrict__ out)
{
    __shared__ float part[4][64];
    __shared__ float comb[65];
    __shared__ float h1[32];
    const int b = blockIdx.x;
    const int tid = threadIdx.x;
    const int ch = tid & 63, q = tid >> 6;

    {
        float s = 0.f;
        const float* basep = g_buf3f + (b * 256 + q * 64) * 64 + ch;
#pragma unroll 8
        for (int P = 0; P < 64; P++) s += basep[P * 64];
        part[q][ch] = s;
    }
    __syncthreads();

    if (tid < 64)
        comb[tid] = (part[0][tid] + part[1][tid] + part[2][tid] + part[3][tid])
                  * (1.f / 256.f);
    if (tid == 64) comb[64] = rms[b];
    __syncthreads();

    if (tid < 32) {
        float a = fc1b[tid];
        const float* wr = fc1w + tid * 65;
#pragma unroll
        for (int i = 0; i < 65; i++) a = fmaf(comb[i], wr[i], a);
        h1[tid] = ht(a);
    }
    __syncthreads();

    if (tid < 2) {
        float a = fc2b[tid];
        const float* wr = fc2w + tid * 32;
#pragma unroll
        for (int i = 0; i < 32; i++) a = fmaf(h1[i], wr[i], a);
        out[b * 2 + tid] = a;
    }
}

// ---------------------------------------------------------------------------
extern "C" void kernel_launch(void* const* d_in, const int* in_sizes, int n_in,
                              void* d_out, int out_size)
{
    const float* x     = (const float*)d_in[0];
    const float* rms   = (const float*)d_in[1];
    const float* w1    = (const float*)d_in[2];
    const float* g1    = (const float*)d_in[3];
    const float* b1    = (const float*)d_in[4];
    const float* m1    = (const float*)d_in[5];
    const float* v1    = (const float*)d_in[6];
    const float* w2    = (const float*)d_in[7];
    const float* g2    = (const float*)d_in[8];
    const float* b2    = (const float*)d_in[9];
    const float* m2    = (const float*)d_in[10];
    const float* v2    = (const float*)d_in[11];
    const float* w3    = (const float*)d_in[12];
    const float* g3    = (const float*)d_in[13];
    const float* b3    = (const float*)d_in[14];
    const float* m3    = (const float*)d_in[15];
    const float* v3    = (const float*)d_in[16];
    const float* fc1w  = (const float*)d_in[17];
    const float* fc1b  = (const float*)d_in[18];
    const float* fc2w  = (const float*)d_in[19];
    const float* fc2b  = (const float*)d_in[20];
    float* out = (float*)d_out;

    const int k3_smem = 20480 + 259 * 19 * 8;   // 59848 B
    cudaFuncSetAttribute(k3, cudaFuncAttributeMaxDynamicSharedMemorySize, k3_smem);

    k0a<<<1, 256>>>(w1, g1, b1, m1, v1, w2, g2, b2, m2, v2);
    k0b<<<1, 256>>>(w3, g3, b3, m3, v3);
    k1<<<dim3(16, 128), 128>>>(x);
    k2<<<dim3(8, 256), 256>>>();
    k3<<<dim3(4, 256), 256, k3_smem>>>();
    k4<<<256, 256>>>(rms, fc1w, fc1b, fc2w, fc2b, out);
}

// round 16
// speedup vs baseline: 1.4766x; 1.0345x over previous
#include <cuda_runtime.h>
#include <cuda_bf16.h>
#include <cstdint>

#define EPS 1e-5f
typedef unsigned long long ull;
struct ull2x { ull x, y; };

// ---------------------------------------------------------------------------
// Buffers
// ---------------------------------------------------------------------------
// stage1 output: interleaved bf16 hi/lo planes. [b][ch][pos/2] -> uint2(h,l)
static __device__ uint2 g_x1hl[256 * 16 * 2048];
// stage2 output: [b][pos][ch/2] -> uint2(h,l)
static __device__ uint2 g_x2hl[256 * 1024 * 16];
// stage3 pooled ht output f32 [b][pos][ch]
static __device__ float g_buf3f[256 * 256 * 64];

// k1 packed weights (batch-pair lanes)
static __device__ ull pw1[16 * 17];
static __device__ ull psh1[16];

// BN epilogue params for stages 2/3
static __device__ float psc2f[32], pshf2[32];
static __device__ float psc3f[64], pshf3[64];

// B fragments, mma.m16n8k16 per-lane layout. K-orders:
//   conv2: e = ci*10 + k (k=9 is zero pad), K=160
//   conv3: e = k*32 + ci, K=160
static __device__ uint2 gB2frag[10 * 4 * 32];
static __device__ uint2 gB3frag[10 * 8 * 32];

__device__ __forceinline__ float ht(float x) { return fminf(1.f, fmaxf(-1.f, x)); }
__device__ __forceinline__ float sgn(float x) { return (x > 0.f) ? 1.f : ((x < 0.f) ? -1.f : 0.f); }

__device__ __forceinline__ ull fma2(ull a, ull b, ull c) {
    ull d; asm("fma.rn.f32x2 %0, %1, %2, %3;" : "=l"(d) : "l"(a), "l"(b), "l"(c)); return d;
}
__device__ __forceinline__ ull pk(float lo, float hi) {
    ull d; asm("mov.b64 %0, {%1, %2};" : "=l"(d) : "f"(lo), "f"(hi)); return d;
}
__device__ __forceinline__ void upk(ull d, float& lo, float& hi) {
    asm("mov.b64 {%0, %1}, %2;" : "=f"(lo), "=f"(hi) : "l"(d));
}
// pack two f32 -> bf16x2 (first arg in low half)
__device__ __forceinline__ uint32_t cvt2bf(float lo, float hi) {
    uint32_t d; asm("cvt.rn.bf16x2.f32 %0, %1, %2;" : "=r"(d) : "f"(hi), "f"(lo)); return d;
}
__device__ __forceinline__ float bf_lo(uint32_t h) { return __uint_as_float(h << 16); }
__device__ __forceinline__ float bf_hi(uint32_t h) { return __uint_as_float(h & 0xffff0000u); }

__device__ __forceinline__ void mma16816(float* d, uint32_t a0, uint32_t a1,
                                         uint32_t a2, uint32_t a3,
                                         uint32_t b0, uint32_t b1) {
    asm volatile(
        "mma.sync.aligned.m16n8k16.row.col.f32.bf16.bf16.f32 "
        "{%0,%1,%2,%3}, {%4,%5,%6,%7}, {%8,%9}, {%0,%1,%2,%3};"
        : "+f"(d[0]), "+f"(d[1]), "+f"(d[2]), "+f"(d[3])
        : "r"(a0), "r"(a1), "r"(a2), "r"(a3), "r"(b0), "r"(b1));
}

__device__ __forceinline__ uint2 split2u(float y0, float y1) {
    uint2 r;
    r.x = cvt2bf(y0, y1);
    r.y = cvt2bf(y0 - bf_lo(r.x), y1 - bf_hi(r.x));
    return r;
}

// ---------------------------------------------------------------------------
// k0a: k1 weight pack + stage2 BN params + B2 fragments (e = ci*10 + k)
// ---------------------------------------------------------------------------
__global__ void k0a(
    const float* __restrict__ w1,
    const float* __restrict__ g1, const float* __restrict__ b1,
    const float* __restrict__ m1, const float* __restrict__ v1,
    const float* __restrict__ w2,
    const float* __restrict__ g2, const float* __restrict__ b2,
    const float* __restrict__ m2, const float* __restrict__ v2)
{
    const int tid = threadIdx.x;
    for (int i = tid; i < 272; i += 256) {
        int ch = i / 17, k = i % 17;
        float s = g1[ch] * rsqrtf(v1[ch] + EPS);
        float v = w1[ch * 17 + k] * s;
        pw1[i] = pk(v, v);
    }
    if (tid < 16) {
        float s = g1[tid] * rsqrtf(v1[tid] + EPS);
        float t = b1[tid] - m1[tid] * s;
        psh1[tid] = pk(t, t);
    }
    if (tid < 32) {
        float s = g2[tid] * rsqrtf(v2[tid] + EPS);
        psc2f[tid] = s;
        pshf2[tid] = b2[tid] - m2[tid] * s;
    }
    for (int i = tid; i < 10 * 4 * 32; i += 256) {
        int kc = i >> 7, nt = (i >> 5) & 3, l = i & 31;
        int co = nt * 8 + (l >> 2);
        int k0 = kc * 16 + 2 * (l & 3);
        float v[4];
#pragma unroll
        for (int j = 0; j < 4; j++) {
            int e = k0 + (j >> 1) * 8 + (j & 1);
            int ci = e / 10, kk = e % 10;
            v[j] = (kk < 9) ? sgn(w2[co * 144 + ci * 9 + kk]) : 0.f;
        }
        uint2 r;
        r.x = cvt2bf(v[0], v[1]);
        r.y = cvt2bf(v[2], v[3]);
        gB2frag[i] = r;
    }
}

// ---------------------------------------------------------------------------
// k0b: stage3 BN params + B3 fragments (e = k*32 + ci)
// ---------------------------------------------------------------------------
__global__ void k0b(
    const float* __restrict__ w3,
    const float* __restrict__ g3, const float* __restrict__ b3,
    const float* __restrict__ m3, const float* __restrict__ v3)
{
    const int tid = threadIdx.x;
    if (tid < 64) {
        float s = g3[tid] * rsqrtf(v3[tid] + EPS);
        psc3f[tid] = s;
        pshf3[tid] = b3[tid] - m3[tid] * s;
    }
    for (int i = tid; i < 10 * 8 * 32; i += 256) {
        int kc = i >> 8, nt = (i >> 5) & 7, l = i & 31;
        int co = nt * 8 + (l >> 2);
        int k0 = kc * 16 + 2 * (l & 3);
        float v[4];
#pragma unroll
        for (int j = 0; j < 4; j++) {
            int e = k0 + (j >> 1) * 8 + (j & 1);
            int k = e >> 5, ci = e & 31;
            v[j] = sgn(w3[co * 160 + ci * 5 + k]);
        }
        uint2 r;
        r.x = cvt2bf(v[0], v[1]);
        r.y = cvt2bf(v[2], v[3]);
        gB3frag[i] = r;
    }
}

// ---------------------------------------------------------------------------
// Kernel 1: conv1 + BN + ht + pool (FFMA2, batch-pair lanes). Outputs
// interleaved hi/lo uint2 planes [b][ch][pos/2].
// ---------------------------------------------------------------------------
__global__ __launch_bounds__(128) void k1(const float* __restrict__ x)
{
    __shared__ ull xs[1040];
    __shared__ ull ws[272];
    __shared__ ull sh[16];

    const int bp = blockIdx.y;
    const int p0 = blockIdx.x * 256;
    const int tid = threadIdx.x;

    for (int i = tid; i < 272; i += 128) ws[i] = pw1[i];
    if (tid < 16) sh[tid] = psh1[tid];

    const float* xb0 = x + (2 * bp) * 16384;
    const float* xb1 = xb0 + 16384;
    const int base = 4 * p0 - 8;
    for (int i = tid; i < 1039; i += 128) {
        int gi = base + i;
        xs[i] = (gi >= 0 && gi < 16384) ? pk(xb0[gi], xb1[gi]) : 0ull;
    }
    __syncthreads();

    ull xp[23];
#pragma unroll
    for (int j = 0; j < 11; j++) {
        ull2x t = *(const ull2x*)&xs[8 * tid + 2 * j];
        xp[2 * j] = t.x; xp[2 * j + 1] = t.y;
    }
    xp[22] = xs[8 * tid + 22];

    const int pidx = blockIdx.x * 128 + tid;   // pos/2 index
#pragma unroll 1
    for (int ch = 0; ch < 16; ch++) {
        ull h2 = sh[ch];
        ull a[4] = {h2, h2, h2, h2};
#pragma unroll
        for (int k = 0; k < 17; k++) {
            ull w = ws[ch * 17 + k];
#pragma unroll
            for (int j = 0; j < 4; j++) a[j] = fma2(w, xp[2 * j + k], a[j]);
        }
        float lo[4], hi[4];
#pragma unroll
        for (int j = 0; j < 4; j++) upk(a[j], lo[j], hi[j]);
        g_x1hl[((2 * bp) * 16 + ch) * 2048 + pidx] =
            split2u(ht(fmaxf(lo[0], lo[1])), ht(fmaxf(lo[2], lo[3])));
        g_x1hl[((2 * bp + 1) * 16 + ch) * 2048 + pidx] =
            split2u(ht(fmaxf(hi[0], hi[1])), ht(fmaxf(hi[2], hi[3])));
    }
}

// ---------------------------------------------------------------------------
// Kernel 2 (R13 structure): mma.sync on separate hs/ls smem planes, B in
// smem. 256 thr, 8 warps, warp owns one m16 tile. Shfl-pool epilogue.
// grid (16, 256).
// ---------------------------------------------------------------------------
struct SmemK2 { uint32_t hs[16 * 133]; uint32_t ls[16 * 133]; };

__global__ __launch_bounds__(256) void k2()
{
    __shared__ SmemK2 sm;
    __shared__ uint2 Bsm[10 * 4 * 32];   // 10 KB

    const int tile = blockIdx.x;   // 0..15
    const int b = blockIdx.y;
    const int tid = threadIdx.x;
    const int w = tid >> 5, l = tid & 31;
    const int g = l >> 2, t = l & 3;

    for (int i = tid; i < 1280; i += 256) Bsm[i] = gB2frag[i];

    {
        const uint2* in = g_x1hl + b * 16 * 2048;
        const int ubase = tile * 128 - 2;
        for (int i = tid; i < 16 * 132; i += 256) {
            int row = i / 132, c = i % 132;
            int gu = ubase + c;
            uint2 v = (gu >= 0 && gu < 2048) ? in[row * 2048 + gu]
                                             : make_uint2(0u, 0u);
            sm.hs[row * 133 + c] = v.x;
            sm.ls[row * 133 + c] = v.y;
        }
    }
    __syncthreads();

    float D[4][4];
#pragma unroll
    for (int nt = 0; nt < 4; nt++)
#pragma unroll
        for (int j = 0; j < 4; j++) D[nt][j] = 0.f;

    const int r = w * 16 + g;   // warp owns m-tile w (16 rows)

#pragma unroll 2
    for (int kc = 0; kc < 10; kc++) {
        uint2 Bf[4];
#pragma unroll
        for (int nt = 0; nt < 4; nt++) Bf[nt] = Bsm[(kc * 4 + nt) * 32 + l];

        const int e0 = kc * 16 + 2 * t;
        const int e8 = e0 + 8;
        const int o0 = (e0 / 10) * 133 + (e0 % 10) / 2;
        const int o8 = (e8 / 10) * 133 + (e8 % 10) / 2;

        uint32_t a0 = sm.hs[o0 + r], a1 = sm.hs[o0 + r + 8];
        uint32_t a2 = sm.hs[o8 + r], a3 = sm.hs[o8 + r + 8];
        uint32_t c0 = sm.ls[o0 + r], c1 = sm.ls[o0 + r + 8];
        uint32_t c2 = sm.ls[o8 + r], c3 = sm.ls[o8 + r + 8];
#pragma unroll
        for (int nt = 0; nt < 4; nt++)
            mma16816(D[nt], a0, a1, a2, a3, Bf[nt].x, Bf[nt].y);
#pragma unroll
        for (int nt = 0; nt < 4; nt++)
            mma16816(D[nt], c0, c1, c2, c3, Bf[nt].x, Bf[nt].y);
    }

    // Register epilogue: BN + ht, pool rows (r, r^1) via shfl_xor(4).
    const bool writer = ((l & 4) == 0);     // even g
    const int prl = w * 8 + (g >> 1);       // local pooled row for d[0],d[1]
#pragma unroll
    for (int nt = 0; nt < 4; nt++) {
        const int c0 = nt * 8 + 2 * t, c1 = c0 + 1;
        const float s0 = psc2f[c0], b0 = pshf2[c0];
        const float s1 = psc2f[c1], b1 = pshf2[c1];
        float y0 = ht(fmaf(D[nt][0], s0, b0));
        float y1 = ht(fmaf(D[nt][1], s1, b1));
        float y2 = ht(fmaf(D[nt][2], s0, b0));
        float y3 = ht(fmaf(D[nt][3], s1, b1));
        float p0 = fmaxf(y0, __shfl_xor_sync(0xffffffffu, y0, 4));
        float p1 = fmaxf(y1, __shfl_xor_sync(0xffffffffu, y1, 4));
        float p2 = fmaxf(y2, __shfl_xor_sync(0xffffffffu, y2, 4));
        float p3 = fmaxf(y3, __shfl_xor_sync(0xffffffffu, y3, 4));
        if (writer) {
            const int cp = nt * 4 + t;
            const int o = (b * 1024 + tile * 64 + prl) * 16 + cp;
            g_x2hl[o] = split2u(p0, p1);
            g_x2hl[o + 4 * 16] = split2u(p2, p3);
        }
    }
}

// ---------------------------------------------------------------------------
// Kernel 3: conv3 via mma.sync, interleaved uint2 smem (stride 19), row-
// permuted M mapping, register epilogue with float2 stores.
// K-order e = k*32 + ci. 256 thr, grid (4, 256). Dynamic smem.
// ---------------------------------------------------------------------------
__global__ __launch_bounds__(256) void k3()
{
    extern __shared__ char dyn3[];
    uint2* Bsm = (uint2*)dyn3;                     // 2560 uint2 = 20480 B
    uint2* hl = (uint2*)(dyn3 + 20480);            // 259*19 uint2

    const int tile = blockIdx.x;   // 0..3
    const int b = blockIdx.y;
    const int tid = threadIdx.x;
    const int w = tid >> 5, l = tid & 31;
    const int g = l >> 2, t = l & 3;

    for (int i = tid; i < 2560; i += 256) Bsm[i] = gB3frag[i];

    const int rbase = tile * 256 - 2;
    for (int i = tid; i < 259 * 16; i += 256) {
        int row = i >> 4, cp = i & 15;
        int gi = rbase + row;
        hl[row * 19 + cp] = (gi >= 0 && gi < 1024)
                          ? g_x2hl[(b * 1024 + gi) * 16 + cp]
                          : make_uint2(0u, 0u);
    }
    __syncthreads();

    float D[8][4];
#pragma unroll
    for (int nt = 0; nt < 8; nt++)
#pragma unroll
        for (int j = 0; j < 4; j++) D[nt][j] = 0.f;

    const int pbase = w * 16 + 2 * g;   // conv pos for row g; row g+8 = pbase+1

#pragma unroll 2
    for (int kc = 0; kc < 10; kc++) {
        uint2 Bf[8];
#pragma unroll
        for (int nt = 0; nt < 8; nt++) Bf[nt] = Bsm[(kc * 8 + nt) * 32 + l];

        const int e0 = kc * 16 + 2 * t;
        const int k = e0 >> 5;
        const int u0 = (e0 & 31) >> 1;

        const int ra = (2 * pbase + k) * 19 + u0;   // row g
        const int rb = ra + 2 * 19;                 // row g+8 (pos+1)
        uint2 A0 = hl[ra],     A1 = hl[rb];
        uint2 A2 = hl[ra + 4], A3 = hl[rb + 4];
#pragma unroll
        for (int nt = 0; nt < 8; nt++)
            mma16816(D[nt], A0.x, A1.x, A2.x, A3.x, Bf[nt].x, Bf[nt].y);
#pragma unroll
        for (int nt = 0; nt < 8; nt++)
            mma16816(D[nt], A0.y, A1.y, A2.y, A3.y, Bf[nt].x, Bf[nt].y);
    }

    // Register epilogue: BN + ht, in-thread pooling, float2 stores.
    const int P = b * 256 + tile * 64 + w * 8 + g;   // pooled position
#pragma unroll
    for (int nt = 0; nt < 8; nt++) {
        const int c0 = nt * 8 + 2 * t, c1 = c0 + 1;
        const float s0 = psc3f[c0], b0 = pshf3[c0];
        const float s1 = psc3f[c1], b1 = pshf3[c1];
        float pa = fmaxf(ht(fmaf(D[nt][0], s0, b0)), ht(fmaf(D[nt][2], s0, b0)));
        float pb = fmaxf(ht(fmaf(D[nt][1], s1, b1)), ht(fmaf(D[nt][3], s1, b1)));
        *(float2*)&g_buf3f[P * 64 + c0] = make_float2(pa, pb);
    }
}

// ---------------------------------------------------------------------------
// Kernel 4: mean over 256 pooled pos, concat rms, fc1 + ht, fc2. 256 threads.
// ---------------------------------------------------------------------------
__global__ __launch_bounds__(256) void k4(
    const float* __restrict__ rms,
    const float* __restrict__ fc1w, const float* __restrict__ fc1b,
    const float* __restrict__ fc2w, const float* __restrict__ fc2b,
    float* __restrict__ out)
{
    __shared__ float part[4][64];
    __shared__ float comb[65];
    __shared__ float h1[32];
    const int b = blockIdx.x;
    const int tid = threadIdx.x;
    const int ch = tid & 63, q = tid >> 6;

    {
        float s = 0.f;
        const float* basep = g_buf3f + (b * 256 + q * 64) * 64 + ch;
#pragma unroll 8
        for (int P = 0; P < 64; P++) s += basep[P * 64];
        part[q][ch] = s;
    }
    __syncthreads();

    if (tid < 64)
        comb[tid] = (part[0][tid] + part[1][tid] + part[2][tid] + part[3][tid])
                  * (1.f / 256.f);
    if (tid == 64) comb[64] = rms[b];
    __syncthreads();

    if (tid < 32) {
        float a = fc1b[tid];
        const float* wr = fc1w + tid * 65;
#pragma unroll
        for (int i = 0; i < 65; i++) a = fmaf(comb[i], wr[i], a);
        h1[tid] = ht(a);
    }
    __syncthreads();

    if (tid < 2) {
        float a = fc2b[tid];
        const float* wr = fc2w + tid * 32;
#pragma unroll
        for (int i = 0; i < 32; i++) a = fmaf(h1[i], wr[i], a);
        out[b * 2 + tid] = a;
    }
}

// ---------------------------------------------------------------------------
extern "C" void kernel_launch(void* const* d_in, const int* in_sizes, int n_in,
                              void* d_out, int out_size)
{
    const float* x     = (const float*)d_in[0];
    const float* rms   = (const float*)d_in[1];
    const float* w1    = (const float*)d_in[2];
    const float* g1    = (const float*)d_in[3];
    const float* b1    = (const float*)d_in[4];
    const float* m1    = (const float*)d_in[5];
    const float* v1    = (const float*)d_in[6];
    const float* w2    = (const float*)d_in[7];
    const float* g2    = (const float*)d_in[8];
    const float* b2    = (const float*)d_in[9];
    const float* m2    = (const float*)d_in[10];
    const float* v2    = (const float*)d_in[11];
    const float* w3    = (const float*)d_in[12];
    const float* g3    = (const float*)d_in[13];
    const float* b3    = (const float*)d_in[14];
    const float* m3    = (const float*)d_in[15];
    const float* v3    = (const float*)d_in[16];
    const float* fc1w  = (const float*)d_in[17];
    const float* fc1b  = (const float*)d_in[18];
    const float* fc2w  = (const float*)d_in[19];
    const float* fc2b  = (const float*)d_in[20];
    float* out = (float*)d_out;

    const int k3_smem = 20480 + 259 * 19 * 8;   // 59848 B
    cudaFuncSetAttribute(k3, cudaFuncAttributeMaxDynamicSharedMemorySize, k3_smem);

    k0a<<<1, 256>>>(w1, g1, b1, m1, v1, w2, g2, b2, m2, v2);
    k0b<<<1, 256>>>(w3, g3, b3, m3, v3);
    k1<<<dim3(16, 128), 128>>>(x);
    k2<<<dim3(16, 256), 256>>>();
    k3<<<dim3(4, 256), 256, k3_smem>>>();
    k4<<<256, 256>>>(rms, fc1w, fc1b, fc2w, fc2b, out);
}